// round 9
// baseline (speedup 1.0000x reference)
#include <cuda_runtime.h>
#include <cuda_fp16.h>
#include <cstdint>

// Problem constants
#define HW   4096
#define CCH  64
#define CQD  8
#define NBAT 4
#define NSPL 4          // denom j-split
#define NS   4          // attn key-split
#define NC   (HW / (NS * 128))   // chunks per attn block = 8
#define PSZ  (NBAT * CCH * HW)
#define L2E  1.4426950408889634f

// Scratch (device globals — no allocation allowed)
__device__ __half g_Qh[NBAT * HW * CQD];      // [b][m][8] fp16, pre-scaled by log2(e)
__device__ __half g_Kh[NBAT * HW * CQD];      // [b][n][8] fp16
__device__ __half g_Vh[NBAT * CCH * HW];      // [b][c][m] fp16 (vscale: *= 4096/denom[m])
__device__ float  g_dpart[NSPL * NBAT * HW];  // per-split softmax denominators
__device__ float  g_Dp[NS * PSZ];             // attn split partials [s][b][c][n]

// ---------------------------------------------------------------------------
// helpers
// ---------------------------------------------------------------------------
__device__ __forceinline__ unsigned long long pack2(float lo, float hi) {
    unsigned long long r;
    asm("mov.b64 %0, {%1, %2};" : "=l"(r) : "f"(lo), "f"(hi));
    return r;
}
__device__ __forceinline__ void unpack2(unsigned long long v, float& lo, float& hi) {
    asm("mov.b64 {%0, %1}, %2;" : "=f"(lo), "=f"(hi) : "l"(v));
}
__device__ __forceinline__ unsigned long long fma2(unsigned long long a,
                                                   unsigned long long b,
                                                   unsigned long long c) {
    unsigned long long d;
    asm("fma.rn.f32x2 %0, %1, %2, %3;" : "=l"(d) : "l"(a), "l"(b), "l"(c));
    return d;
}
__device__ __forceinline__ unsigned long long add2(unsigned long long a,
                                                   unsigned long long b) {
    unsigned long long d;
    asm("add.rn.f32x2 %0, %1, %2;" : "=l"(d) : "l"(a), "l"(b));
    return d;
}
__device__ __forceinline__ uint32_t smem_u32(const void* p) {
    uint32_t a;
    asm("{ .reg .u64 t; cvta.to.shared.u64 t, %1; cvt.u32.u64 %0, t; }" : "=r"(a) : "l"(p));
    return a;
}
__device__ __forceinline__ void ldsm2(uint32_t* r, uint32_t addr) {
    asm volatile("ldmatrix.sync.aligned.m8n8.x2.shared.b16 {%0,%1}, [%2];"
                 : "=r"(r[0]), "=r"(r[1]) : "r"(addr));
}
__device__ __forceinline__ void ldsm4(uint32_t* r, uint32_t addr) {
    asm volatile("ldmatrix.sync.aligned.m8n8.x4.shared.b16 {%0,%1,%2,%3}, [%4];"
                 : "=r"(r[0]), "=r"(r[1]), "=r"(r[2]), "=r"(r[3]) : "r"(addr));
}
__device__ __forceinline__ void mma8(float& d0, float& d1, float& d2, float& d3,
                                     const uint32_t* a, uint32_t b) {
    asm volatile("mma.sync.aligned.m16n8k8.row.col.f32.f16.f16.f32 "
                 "{%0,%1,%2,%3}, {%4,%5}, {%6}, {%0,%1,%2,%3};"
                 : "+f"(d0), "+f"(d1), "+f"(d2), "+f"(d3)
                 : "r"(a[0]), "r"(a[1]), "r"(b));
}
__device__ __forceinline__ void mma16(float* d, const uint32_t* a,
                                      uint32_t b0, uint32_t b1) {
    asm volatile("mma.sync.aligned.m16n8k16.row.col.f32.f16.f16.f32 "
                 "{%0,%1,%2,%3}, {%4,%5,%6,%7}, {%8,%9}, {%0,%1,%2,%3};"
                 : "+f"(d[0]), "+f"(d[1]), "+f"(d[2]), "+f"(d[3])
                 : "r"(a[0]), "r"(a[1]), "r"(a[2]), "r"(a[3]), "r"(b0), "r"(b1));
}
__device__ __forceinline__ uint32_t cvt_h2(float lo, float hi) {
    uint32_t r;
    asm("cvt.rn.f16x2.f32 %0, %1, %2;" : "=r"(r) : "f"(hi), "f"(lo));
    return r;
}
__device__ __forceinline__ uint32_t h2ex2(uint32_t a) {
    uint32_t r;
    asm("ex2.approx.f16x2 %0, %1;" : "=r"(r) : "r"(a));
    return r;
}
__device__ __forceinline__ uint32_t hadd2_(uint32_t a, uint32_t b) {
    uint32_t r;
    asm("add.f16x2 %0, %1, %2;" : "=r"(r) : "r"(a), "r"(b));
    return r;
}
__device__ __forceinline__ void cp16(uint32_t smem, const void* g) {
    asm volatile("cp.async.cg.shared.global [%0], [%1], 16;" :: "r"(smem), "l"(g));
}
#define CP_COMMIT() asm volatile("cp.async.commit_group;" ::: "memory")
#define CP_WAIT(n)  asm volatile("cp.async.wait_group %0;" :: "n"(n) : "memory")

// ---------------------------------------------------------------------------
// Kernel 1: QKV projections, v2.
//   4 threads per pixel WITHIN one warp: j = t&3, px = t>>2.
//   Thread j reads c-half (j&1) only (32 LDG, half the chain) and accumulates
//   V channels [32*(j>>1), +32); j<2 also accumulate Q, j>=2 K.
//   Halves combined with shfl_xor(1); V staged in smem for coalesced stores.
// ---------------------------------------------------------------------------
__global__ __launch_bounds__(256) void qkv_kernel(
    const float* __restrict__ x,
    const float* __restrict__ Wq, const float* __restrict__ bq,
    const float* __restrict__ Wk, const float* __restrict__ bk,
    const float* __restrict__ Wv, const float* __restrict__ bv)
{
    __shared__ float WqT[CCH][CQD];
    __shared__ float WkT[CCH][CQD];
    __shared__ float WvT[CCH][CCH];
    __shared__ __half Vstage[CCH][64];     // [c][px]  8 KB

    const int t = threadIdx.x;
    for (int i = t; i < CCH * CQD; i += 256) {
        int o = i / CCH, c = i % CCH;
        WqT[c][o] = Wq[i] * L2E;           // fold log2(e) into Q
        WkT[c][o] = Wk[i];
    }
    for (int i = t; i < CCH * CCH; i += 256) {
        int o = i / CCH, c = i % CCH;
        WvT[c][o] = Wv[i];
    }
    __syncthreads();

    const int b  = blockIdx.y;
    const int px = t >> 2;                 // 0..63
    const int j  = t & 3;
    const int ch = j & 1;                  // c half this thread reads
    const int vg = j >> 1;                 // V output group (32 channels)
    const int n0 = blockIdx.x * 64;
    const int n  = n0 + px;
    const float* xp = x + (size_t)b * CCH * HW + (size_t)ch * 32 * HW + n;

    unsigned long long vacc[16], qk[4];
#pragma unroll
    for (int k = 0; k < 16; k++)
        vacc[k] = ch ? 0ULL : pack2(bv[32 * vg + 2 * k], bv[32 * vg + 2 * k + 1]);
    if (j == 0) {
#pragma unroll
        for (int k = 0; k < 4; k++) qk[k] = pack2(bq[2 * k] * L2E, bq[2 * k + 1] * L2E);
    } else if (j == 2) {
#pragma unroll
        for (int k = 0; k < 4; k++) qk[k] = pack2(bk[2 * k], bk[2 * k + 1]);
    } else {
#pragma unroll
        for (int k = 0; k < 4; k++) qk[k] = 0ULL;
    }

#pragma unroll 8
    for (int i = 0; i < 32; i++) {
        const int c = ch * 32 + i;
        float xv = xp[(size_t)i * HW];
        unsigned long long xx = pack2(xv, xv);
        const unsigned long long* wv2 = (const unsigned long long*)&WvT[c][32 * vg];
#pragma unroll
        for (int k = 0; k < 16; k++) vacc[k] = fma2(xx, wv2[k], vacc[k]);
        const unsigned long long* wqk2 = (j < 2)
            ? (const unsigned long long*)WqT[c]
            : (const unsigned long long*)WkT[c];
#pragma unroll
        for (int k = 0; k < 4; k++) qk[k] = fma2(xx, wqk2[k], qk[k]);
    }

    // combine the two c-halves (partner = lane^1, same pixel & role group)
#pragma unroll
    for (int k = 0; k < 16; k++)
        vacc[k] = add2(vacc[k], __shfl_xor_sync(0xFFFFFFFFu, vacc[k], 1));
#pragma unroll
    for (int k = 0; k < 4; k++)
        qk[k] = add2(qk[k], __shfl_xor_sync(0xFFFFFFFFu, qk[k], 1));

    // Q / K stores (lanes j==0 / j==2): 8 lanes x 16B = 128B contiguous
    if (j == 0 || j == 2) {
        uint32_t u[4];
#pragma unroll
        for (int k = 0; k < 4; k++) {
            float lo, hi;
            unpack2(qk[k], lo, hi);
            u[k] = cvt_h2(lo, hi);
        }
        __half* dst = (j == 0) ? g_Qh : g_Kh;
        *(uint4*)(dst + ((size_t)b * HW + n) * CQD) = make_uint4(u[0], u[1], u[2], u[3]);
        // V stage (even lanes own the complete sums)
#pragma unroll
        for (int k = 0; k < 16; k++) {
            float lo, hi;
            unpack2(vacc[k], lo, hi);
            Vstage[32 * vg + 2 * k][px]     = __float2half(lo);
            Vstage[32 * vg + 2 * k + 1][px] = __float2half(hi);
        }
    }
    __syncthreads();

    // coalesced V flush: each c-row = 32 uints = 128B
    const uint32_t* Vs = (const uint32_t*)Vstage;
#pragma unroll
    for (int idx = t; idx < CCH * 32; idx += 256) {
        const int c = idx >> 5, p2 = idx & 31;
        ((uint32_t*)(g_Vh + ((size_t)b * CCH + c) * HW + n0))[p2] = Vs[idx];
    }
}

// ---------------------------------------------------------------------------
// Kernel 2: softmax denominators via MMA scores + f16x2 ex2.
// ---------------------------------------------------------------------------
__global__ __launch_bounds__(256) void denom_kernel()
{
    __shared__ __align__(16) uint8_t sm[4096];
    const uint32_t smb = smem_u32(sm);

    const int t = threadIdx.x, w = t >> 5, l = t & 31;
    const int b = blockIdx.z, s = blockIdx.y;
    const int mbase = blockIdx.x * 128;

    const uint4* Qg = (const uint4*)(g_Qh + (size_t)b * HW * CQD);
    const uint4* Kg = (const uint4*)(g_Kh + (size_t)b * HW * CQD);

    if (t < 128) *(uint4*)(sm + t * 16) = Qg[mbase + t];
    __syncthreads();
    uint32_t qa[2];
    ldsm2(qa, smb + (16 * w + (l & 15)) * 16);

    float rs0 = 0.0f, rs1 = 0.0f;
    for (int ch = 0; ch < (HW / NSPL) / 128; ch++) {
        const int nn0 = s * (HW / NSPL) + ch * 128;
        __syncthreads();
        if (t < 128) *(uint4*)(sm + 2048 + t * 16) = Kg[nn0 + t];
        __syncthreads();
        uint32_t kb[16];
        ldsm4(kb + 0,  smb + 2048 + l * 16);
        ldsm4(kb + 4,  smb + 2048 + (32 + l) * 16);
        ldsm4(kb + 8,  smb + 2048 + (64 + l) * 16);
        ldsm4(kb + 12, smb + 2048 + (96 + l) * 16);
        uint32_t a0 = 0u, a1 = 0u;
#pragma unroll
        for (int jj = 0; jj < 16; jj++) {
            float d0 = 0, d1 = 0, d2 = 0, d3 = 0;
            mma8(d0, d1, d2, d3, qa, kb[jj]);
            a0 = hadd2_(a0, h2ex2(cvt_h2(d0, d1)));
            a1 = hadd2_(a1, h2ex2(cvt_h2(d2, d3)));
        }
        float2 f0 = __half22float2(*reinterpret_cast<__half2*>(&a0));
        float2 f1 = __half22float2(*reinterpret_cast<__half2*>(&a1));
        rs0 += f0.x + f0.y;
        rs1 += f1.x + f1.y;
    }
    rs0 += __shfl_xor_sync(0xFFFFFFFFu, rs0, 1);
    rs0 += __shfl_xor_sync(0xFFFFFFFFu, rs0, 2);
    rs1 += __shfl_xor_sync(0xFFFFFFFFu, rs1, 1);
    rs1 += __shfl_xor_sync(0xFFFFFFFFu, rs1, 2);
    if ((l & 3) == 0) {
        const int r = 16 * w + (l >> 2);
        float* dst = g_dpart + ((size_t)s * NBAT + b) * HW + mbase;
        dst[r]     = rs0;
        dst[r + 8] = rs1;
    }
}

// ---------------------------------------------------------------------------
// Kernel 3: prescale V in place (half2): V[c][m] *= 4096/denom[m]
// ---------------------------------------------------------------------------
__global__ __launch_bounds__(256) void vscale_kernel()
{
    const int t = threadIdx.x;
    const int b = blockIdx.y;
    const int m2 = blockIdx.x * 256 + t;
    const int m = 2 * m2;
    float da = g_dpart[(size_t)b * HW + m]
             + g_dpart[((size_t)NBAT + b) * HW + m]
             + g_dpart[((size_t)2 * NBAT + b) * HW + m]
             + g_dpart[((size_t)3 * NBAT + b) * HW + m];
    float db = g_dpart[(size_t)b * HW + m + 1]
             + g_dpart[((size_t)NBAT + b) * HW + m + 1]
             + g_dpart[((size_t)2 * NBAT + b) * HW + m + 1]
             + g_dpart[((size_t)3 * NBAT + b) * HW + m + 1];
    const __half2 inv = __floats2half2_rn(__fdividef(4096.0f, da),
                                          __fdividef(4096.0f, db));
    __half2* Vp = (__half2*)(g_Vh + (size_t)b * CCH * HW) + m2;
#pragma unroll
    for (int c = 0; c < CCH; c++)
        Vp[(size_t)c * (HW / 2)] = __hmul2(Vp[(size_t)c * (HW / 2)], inv);
}

// ---------------------------------------------------------------------------
// Kernel 4: attention aggregation (round-7 version: measured best).
//   Split over keys, cp.async double-buffered V/Q staging.
// ---------------------------------------------------------------------------
#define VSTR  272
#define SM_V0 0
#define SM_V1 17408
#define SM_Q0 34816
#define SM_Q1 36864
#define SM_K  38912
#define SMA_BYTES 40960
#define OSTR  65

__global__ __launch_bounds__(256, 3) void attn_kernel()
{
    __shared__ __align__(16) uint8_t sm[SMA_BYTES];
    const uint32_t smb = smem_u32(sm);

    const int t = threadIdx.x, w = t >> 5, l = t & 31;
    const int s = blockIdx.y;
    const int b = blockIdx.z;
    const int n0 = blockIdx.x * 128;

    const uint4* Kg = (const uint4*)(g_Kh + (size_t)b * HW * CQD);
    const uint4* Qg = (const uint4*)(g_Qh + (size_t)b * HW * CQD);
    const uint4* Vg = (const uint4*)(g_Vh + (size_t)b * CCH * HW);

    if (t < 128) *(uint4*)(sm + SM_K + t * 16) = Kg[n0 + t];

    auto stage = [&](int buf, int m0) {
        const uint32_t vbase = smb + (buf ? SM_V1 : SM_V0);
#pragma unroll
        for (int jj = 0; jj < 4; jj++) {
            int i = t + jj * 256;
            int row = i >> 4, c16 = i & 15;
            cp16(vbase + row * VSTR + c16 * 16,
                 Vg + (size_t)row * (HW / 8) + (m0 >> 3) + c16);
        }
        if (t < 128) cp16(smb + (buf ? SM_Q1 : SM_Q0) + t * 16, Qg + m0 + t);
    };

    stage(0, s * NC * 128);
    CP_COMMIT();

    __syncthreads();
    uint32_t ka[2];
    ldsm2(ka, smb + SM_K + (16 * w + (l & 15)) * 16);

    float dacc[8][4];
#pragma unroll
    for (int ct = 0; ct < 8; ct++)
#pragma unroll
        for (int i = 0; i < 4; i++) dacc[ct][i] = 0.0f;

    for (int chunk = 0; chunk < NC; chunk++) {
        const int buf = chunk & 1;
        if (chunk + 1 < NC) {
            stage(buf ^ 1, (s * NC + chunk + 1) * 128);
            CP_COMMIT();
            CP_WAIT(1);
        } else {
            CP_WAIT(0);
        }
        __syncthreads();

        const uint32_t vbase = smb + (buf ? SM_V1 : SM_V0);
        const uint32_t qbase = smb + (buf ? SM_Q1 : SM_Q0);

        // ---- scores -> P A-frags: mma8 -> cvt f16x2 -> ex2.f16x2 ----
        uint32_t pa[8][4];
#pragma unroll
        for (int half = 0; half < 2; half++) {
            uint32_t qb[8];
            ldsm4(qb + 0, qbase + (64 * half + l) * 16);
            ldsm4(qb + 4, qbase + (64 * half + 32 + l) * 16);
#pragma unroll
            for (int jj = 0; jj < 8; jj++) {
                float d0 = 0, d1 = 0, d2 = 0, d3 = 0;
                mma8(d0, d1, d2, d3, ka, qb[jj]);
                const int jt = 8 * half + jj;
                pa[jt >> 1][(jt & 1) * 2]     = h2ex2(cvt_h2(d0, d1));
                pa[jt >> 1][(jt & 1) * 2 + 1] = h2ex2(cvt_h2(d2, d3));
            }
        }

        // ---- D += P @ V' ----
#pragma unroll
        for (int kk = 0; kk < 8; kk++) {
#pragma unroll
            for (int cp = 0; cp < 4; cp++) {
                uint32_t bb[4];
                ldsm4(bb, vbase
                          + (cp * 16 + ((l >> 4) << 3) + (l & 7)) * VSTR
                          + kk * 32 + ((l >> 3) & 1) * 16);
                mma16(dacc[2 * cp],     pa[kk], bb[0], bb[1]);
                mma16(dacc[2 * cp + 1], pa[kk], bb[2], bb[3]);
            }
        }
        __syncthreads();
    }

    // ---- stage partial D through smem, write [s][b][c][n] coalesced ----
    float* sD = (float*)sm;
    const int r = l >> 2, q = l & 3;
#pragma unroll
    for (int ct = 0; ct < 8; ct++) {
        const int c = ct * 8 + 2 * q;
        sD[(16 * w + r) * OSTR + c]         = dacc[ct][0];
        sD[(16 * w + r) * OSTR + c + 1]     = dacc[ct][1];
        sD[(16 * w + r + 8) * OSTR + c]     = dacc[ct][2];
        sD[(16 * w + r + 8) * OSTR + c + 1] = dacc[ct][3];
    }
    __syncthreads();

    float* dst = g_Dp + (size_t)s * PSZ + (size_t)b * CCH * HW;
#pragma unroll
    for (int i = t; i < 128 * CCH; i += 256) {
        const int c = i >> 7, n = i & 127;
        dst[(size_t)c * HW + n0 + n] = sD[n * OSTR + c];
    }
}

// ---------------------------------------------------------------------------
// Kernel 5: combine split partials + gamma + residual (vectorized)
// ---------------------------------------------------------------------------
__global__ __launch_bounds__(256) void combine_kernel(
    const float* __restrict__ x,
    const float* __restrict__ gamma,
    float* __restrict__ out)
{
    const size_t i = ((size_t)blockIdx.x * 256 + threadIdx.x) * 4;
    const float gm = gamma[0] * (1.0f / 4096.0f);
    float4 a = *(const float4*)(g_Dp + i);
    float4 c = *(const float4*)(g_Dp + PSZ + i);
    float4 d = *(const float4*)(g_Dp + 2 * (size_t)PSZ + i);
    float4 e = *(const float4*)(g_Dp + 3 * (size_t)PSZ + i);
    float4 xv = *(const float4*)(x + i);
    float4 o;
    o.x = gm * ((a.x + c.x) + (d.x + e.x)) + xv.x;
    o.y = gm * ((a.y + c.y) + (d.y + e.y)) + xv.y;
    o.z = gm * ((a.z + c.z) + (d.z + e.z)) + xv.z;
    o.w = gm * ((a.w + c.w) + (d.w + e.w)) + xv.w;
    *(float4*)(out + i) = o;
}

// ---------------------------------------------------------------------------
extern "C" void kernel_launch(void* const* d_in, const int* in_sizes, int n_in,
                              void* d_out, int out_size)
{
    const float* x     = (const float*)d_in[0];
    const float* Wq    = (const float*)d_in[1];
    const float* bq    = (const float*)d_in[2];
    const float* Wk    = (const float*)d_in[3];
    const float* bk    = (const float*)d_in[4];
    const float* Wv    = (const float*)d_in[5];
    const float* bv    = (const float*)d_in[6];
    const float* gamma = (const float*)d_in[7];
    float* out = (float*)d_out;

    qkv_kernel<<<dim3(HW / 64, NBAT), 256>>>(x, Wq, bq, Wk, bk, Wv, bv);
    denom_kernel<<<dim3(HW / 128, NSPL, NBAT), 256>>>();
    vscale_kernel<<<dim3(HW / 512, NBAT), 256>>>();
    attn_kernel<<<dim3(HW / 128, NS, NBAT), 256>>>();
    combine_kernel<<<PSZ / 1024, 256>>>(x, gamma, out);
}

// round 10
// speedup vs baseline: 1.7330x; 1.7330x over previous
#include <cuda_runtime.h>
#include <cuda_fp16.h>
#include <cstdint>

// Problem constants
#define HW   4096
#define CCH  64
#define CQD  8
#define NBAT 4
#define NSPL 4          // denom j-split
#define NS   4          // attn key-split
#define NC   (HW / (NS * 128))   // chunks per attn block = 8
#define PSZ  (NBAT * CCH * HW)
#define L2E  1.4426950408889634f

// Scratch (device globals — no allocation allowed)
__device__ __half g_Qh[NBAT * HW * CQD];      // [b][m][8] fp16, pre-scaled by log2(e)
__device__ __half g_Kh[NBAT * HW * CQD];      // [b][n][8] fp16
__device__ __half g_Vh[NBAT * CCH * HW];      // [b][c][m] fp16 (vscale: *= 4096/denom[m])
__device__ float  g_dpart[NSPL * NBAT * HW];  // per-split softmax denominators
__device__ float  g_Dp[NS * PSZ];             // attn split partials [s][b][c][n]

// ---------------------------------------------------------------------------
// helpers
// ---------------------------------------------------------------------------
__device__ __forceinline__ uint32_t smem_u32(const void* p) {
    uint32_t a;
    asm("{ .reg .u64 t; cvta.to.shared.u64 t, %1; cvt.u32.u64 %0, t; }" : "=r"(a) : "l"(p));
    return a;
}
__device__ __forceinline__ void ldsm2(uint32_t* r, uint32_t addr) {
    asm volatile("ldmatrix.sync.aligned.m8n8.x2.shared.b16 {%0,%1}, [%2];"
                 : "=r"(r[0]), "=r"(r[1]) : "r"(addr));
}
__device__ __forceinline__ void ldsm4(uint32_t* r, uint32_t addr) {
    asm volatile("ldmatrix.sync.aligned.m8n8.x4.shared.b16 {%0,%1,%2,%3}, [%4];"
                 : "=r"(r[0]), "=r"(r[1]), "=r"(r[2]), "=r"(r[3]) : "r"(addr));
}
__device__ __forceinline__ void ldsm4t(uint32_t* r, uint32_t addr) {
    asm volatile("ldmatrix.sync.aligned.m8n8.x4.trans.shared.b16 {%0,%1,%2,%3}, [%4];"
                 : "=r"(r[0]), "=r"(r[1]), "=r"(r[2]), "=r"(r[3]) : "r"(addr));
}
__device__ __forceinline__ void mma8(float& d0, float& d1, float& d2, float& d3,
                                     const uint32_t* a, uint32_t b) {
    asm volatile("mma.sync.aligned.m16n8k8.row.col.f32.f16.f16.f32 "
                 "{%0,%1,%2,%3}, {%4,%5}, {%6}, {%0,%1,%2,%3};"
                 : "+f"(d0), "+f"(d1), "+f"(d2), "+f"(d3)
                 : "r"(a[0]), "r"(a[1]), "r"(b));
}
__device__ __forceinline__ void mma16(float* d, const uint32_t* a,
                                      uint32_t b0, uint32_t b1) {
    asm volatile("mma.sync.aligned.m16n8k16.row.col.f32.f16.f16.f32 "
                 "{%0,%1,%2,%3}, {%4,%5,%6,%7}, {%8,%9}, {%0,%1,%2,%3};"
                 : "+f"(d[0]), "+f"(d[1]), "+f"(d[2]), "+f"(d[3])
                 : "r"(a[0]), "r"(a[1]), "r"(a[2]), "r"(a[3]), "r"(b0), "r"(b1));
}
__device__ __forceinline__ uint32_t cvt_h2(float lo, float hi) {
    uint32_t r;
    asm("cvt.rn.f16x2.f32 %0, %1, %2;" : "=r"(r) : "f"(hi), "f"(lo));
    return r;
}
__device__ __forceinline__ uint32_t h2ex2(uint32_t a) {
    uint32_t r;
    asm("ex2.approx.f16x2 %0, %1;" : "=r"(r) : "r"(a));
    return r;
}
__device__ __forceinline__ uint32_t hadd2_(uint32_t a, uint32_t b) {
    uint32_t r;
    asm("add.f16x2 %0, %1, %2;" : "=r"(r) : "r"(a), "r"(b));
    return r;
}
__device__ __forceinline__ void cp16(uint32_t smem, const void* g) {
    asm volatile("cp.async.cg.shared.global [%0], [%1], 16;" :: "r"(smem), "l"(g));
}
#define CP_COMMIT() asm volatile("cp.async.commit_group;" ::: "memory")
#define CP_WAIT(n)  asm volatile("cp.async.wait_group %0;" :: "n"(n) : "memory")

// ---------------------------------------------------------------------------
// Kernel 1: QKV projections as a tensor-core GEMM.
//   D[n][o] = sum_c x[c][n] * Wall[o][c],  Wall = [V(64) | Q*log2e(8) | K(8)]
//   Per block: 128 pixels. A-frags via ldmatrix.trans from f16 x tile;
//   B-frags from f16 W tile (attn-validated pattern). Epilogue adds biases,
//   writes V [c][n] half-coalesced and Q/K [n][8] as uint4 rows.
// SMEM: x @0 (64 x 272B) | W @17408 (80 x 144B) | bias @41472 (80 f32)
//       epilogue sD f32 [128][81] overlays x/W (41472 B)
// ---------------------------------------------------------------------------
#define XSTR  272
#define WSTR  144
#define SM_X  0
#define SM_W  17408
#define SM_BI 41472
#define SDSTR 81

__global__ __launch_bounds__(256) void qkv_kernel(
    const float* __restrict__ x,
    const float* __restrict__ Wq, const float* __restrict__ bq,
    const float* __restrict__ Wk, const float* __restrict__ bk,
    const float* __restrict__ Wv, const float* __restrict__ bv)
{
    __shared__ __align__(16) uint8_t sm[41792];
    const uint32_t smb = smem_u32(sm);

    const int t = threadIdx.x, w = t >> 5, l = t & 31;
    const int b = blockIdx.y;
    const int n0 = blockIdx.x * 128;

    // stage biases (f32, safe region above sD)
    float* bs = (float*)(sm + SM_BI);
    if (t < 80) {
        float v;
        if (t < 64)      v = bv[t];
        else if (t < 72) v = bq[t - 64] * L2E;
        else             v = bk[t - 72];
        bs[t] = v;
    }
    // stage Wall [80][64] -> f16 (rows: 64 V, 8 Q*log2e, 8 K)
#pragma unroll
    for (int idx = t; idx < 80 * 32; idx += 256) {
        const int o = idx >> 5, p = idx & 31;
        float lo, hi;
        if (o < 64)      { lo = Wv[o * 64 + 2 * p];          hi = Wv[o * 64 + 2 * p + 1]; }
        else if (o < 72) { lo = Wq[(o - 64) * 64 + 2 * p] * L2E;
                           hi = Wq[(o - 64) * 64 + 2 * p + 1] * L2E; }
        else             { lo = Wk[(o - 72) * 64 + 2 * p];   hi = Wk[(o - 72) * 64 + 2 * p + 1]; }
        *(uint32_t*)(sm + SM_W + o * WSTR + p * 4) = cvt_h2(lo, hi);
    }
    // stage x tile [64 c][128 n] f32 -> f16 (coalesced float2 reads)
    const float* xb = x + (size_t)b * CCH * HW + n0;
#pragma unroll
    for (int idx = t; idx < 64 * 64; idx += 256) {
        const int c = idx >> 6, p = idx & 63;
        float2 v = *(const float2*)(xb + (size_t)c * HW + 2 * p);
        *(uint32_t*)(sm + SM_X + c * XSTR + p * 4) = cvt_h2(v.x, v.y);
    }
    __syncthreads();

    // ---- GEMM: warp w owns pixel rows 16w..16w+15, all 80 o-cols ----
    float dacc[10][4];
#pragma unroll
    for (int ct = 0; ct < 10; ct++)
#pragma unroll
        for (int i = 0; i < 4; i++) dacc[ct][i] = 0.0f;

    const int nb = 16 * w;
#pragma unroll
    for (int ks = 0; ks < 4; ks++) {
        uint32_t a[4];
        ldsm4t(a, smb + SM_X
                  + ((l & 7) + ((l >> 4) & 1) * 8 + 16 * ks) * XSTR
                  + (nb + ((l >> 3) & 1) * 8) * 2);
#pragma unroll
        for (int ot = 0; ot < 5; ot++) {
            uint32_t bb[4];
            ldsm4(bb, smb + SM_W + (ot * 16 + ((l >> 4) << 3) + (l & 7)) * WSTR
                      + ks * 32 + ((l >> 3) & 1) * 16);
            mma16(dacc[2 * ot],     a, bb[0], bb[1]);
            mma16(dacc[2 * ot + 1], a, bb[2], bb[3]);
        }
    }

    // ---- epilogue: frags -> sD [128 n][81], then coalesced global writes ----
    __syncthreads();
    float* sD = (float*)sm;
    const int r = l >> 2, q = l & 3;
#pragma unroll
    for (int ct = 0; ct < 10; ct++) {
        const int c = ct * 8 + 2 * q;
        sD[(nb + r) * SDSTR + c]         = dacc[ct][0];
        sD[(nb + r) * SDSTR + c + 1]     = dacc[ct][1];
        sD[(nb + r + 8) * SDSTR + c]     = dacc[ct][2];
        sD[(nb + r + 8) * SDSTR + c + 1] = dacc[ct][3];
    }
    __syncthreads();

    // V: [c][n] half, 2 pixels per thread -> 4B stores, 128B/warp
#pragma unroll
    for (int idx = t; idx < 64 * 64; idx += 256) {
        const int c = idx >> 6, p = idx & 63;
        const float bvv = bs[c];
        const float lo = sD[(2 * p) * SDSTR + c] + bvv;
        const float hi = sD[(2 * p + 1) * SDSTR + c] + bvv;
        *(uint32_t*)(g_Vh + ((size_t)b * CCH + c) * HW + n0 + 2 * p) = cvt_h2(lo, hi);
    }
    // Q (rows 64-71) / K (rows 72-79): one uint4 row per pixel
    {
        const int n = t & 127;
        const int base = (t < 128) ? 64 : 72;
        __half* dst = (t < 128) ? g_Qh : g_Kh;
        uint32_t u[4];
#pragma unroll
        for (int jj = 0; jj < 4; jj++)
            u[jj] = cvt_h2(sD[n * SDSTR + base + 2 * jj] + bs[base + 2 * jj],
                           sD[n * SDSTR + base + 2 * jj + 1] + bs[base + 2 * jj + 1]);
        *(uint4*)(dst + ((size_t)b * HW + n0 + n) * CQD) = make_uint4(u[0], u[1], u[2], u[3]);
    }
}

// ---------------------------------------------------------------------------
// Kernel 2: softmax denominators via MMA scores + f16x2 ex2.
// ---------------------------------------------------------------------------
__global__ __launch_bounds__(256) void denom_kernel()
{
    __shared__ __align__(16) uint8_t sm[4096];
    const uint32_t smb = smem_u32(sm);

    const int t = threadIdx.x, w = t >> 5, l = t & 31;
    const int b = blockIdx.z, s = blockIdx.y;
    const int mbase = blockIdx.x * 128;

    const uint4* Qg = (const uint4*)(g_Qh + (size_t)b * HW * CQD);
    const uint4* Kg = (const uint4*)(g_Kh + (size_t)b * HW * CQD);

    if (t < 128) *(uint4*)(sm + t * 16) = Qg[mbase + t];
    __syncthreads();
    uint32_t qa[2];
    ldsm2(qa, smb + (16 * w + (l & 15)) * 16);

    float rs0 = 0.0f, rs1 = 0.0f;
    for (int ch = 0; ch < (HW / NSPL) / 128; ch++) {
        const int nn0 = s * (HW / NSPL) + ch * 128;
        __syncthreads();
        if (t < 128) *(uint4*)(sm + 2048 + t * 16) = Kg[nn0 + t];
        __syncthreads();
        uint32_t kb[16];
        ldsm4(kb + 0,  smb + 2048 + l * 16);
        ldsm4(kb + 4,  smb + 2048 + (32 + l) * 16);
        ldsm4(kb + 8,  smb + 2048 + (64 + l) * 16);
        ldsm4(kb + 12, smb + 2048 + (96 + l) * 16);
        uint32_t a0 = 0u, a1 = 0u;
#pragma unroll
        for (int jj = 0; jj < 16; jj++) {
            float d0 = 0, d1 = 0, d2 = 0, d3 = 0;
            mma8(d0, d1, d2, d3, qa, kb[jj]);
            a0 = hadd2_(a0, h2ex2(cvt_h2(d0, d1)));
            a1 = hadd2_(a1, h2ex2(cvt_h2(d2, d3)));
        }
        float2 f0 = __half22float2(*reinterpret_cast<__half2*>(&a0));
        float2 f1 = __half22float2(*reinterpret_cast<__half2*>(&a1));
        rs0 += f0.x + f0.y;
        rs1 += f1.x + f1.y;
    }
    rs0 += __shfl_xor_sync(0xFFFFFFFFu, rs0, 1);
    rs0 += __shfl_xor_sync(0xFFFFFFFFu, rs0, 2);
    rs1 += __shfl_xor_sync(0xFFFFFFFFu, rs1, 1);
    rs1 += __shfl_xor_sync(0xFFFFFFFFu, rs1, 2);
    if ((l & 3) == 0) {
        const int r = 16 * w + (l >> 2);
        float* dst = g_dpart + ((size_t)s * NBAT + b) * HW + mbase;
        dst[r]     = rs0;
        dst[r + 8] = rs1;
    }
}

// ---------------------------------------------------------------------------
// Kernel 3: prescale V in place (half2): V[c][m] *= 4096/denom[m]
// ---------------------------------------------------------------------------
__global__ __launch_bounds__(256) void vscale_kernel()
{
    const int t = threadIdx.x;
    const int b = blockIdx.y;
    const int m2 = blockIdx.x * 256 + t;
    const int m = 2 * m2;
    float da = g_dpart[(size_t)b * HW + m]
             + g_dpart[((size_t)NBAT + b) * HW + m]
             + g_dpart[((size_t)2 * NBAT + b) * HW + m]
             + g_dpart[((size_t)3 * NBAT + b) * HW + m];
    float db = g_dpart[(size_t)b * HW + m + 1]
             + g_dpart[((size_t)NBAT + b) * HW + m + 1]
             + g_dpart[((size_t)2 * NBAT + b) * HW + m + 1]
             + g_dpart[((size_t)3 * NBAT + b) * HW + m + 1];
    const __half2 inv = __floats2half2_rn(__fdividef(4096.0f, da),
                                          __fdividef(4096.0f, db));
    __half2* Vp = (__half2*)(g_Vh + (size_t)b * CCH * HW) + m2;
#pragma unroll
    for (int c = 0; c < CCH; c++)
        Vp[(size_t)c * (HW / 2)] = __hmul2(Vp[(size_t)c * (HW / 2)], inv);
}

// ---------------------------------------------------------------------------
// Kernel 4: attention aggregation (round-7 version: measured best).
// ---------------------------------------------------------------------------
#define VSTR  272
#define SM_V0 0
#define SM_V1 17408
#define SM_Q0 34816
#define SM_Q1 36864
#define SM_K  38912
#define SMA_BYTES 40960
#define OSTR  65

__global__ __launch_bounds__(256, 3) void attn_kernel()
{
    __shared__ __align__(16) uint8_t sm[SMA_BYTES];
    const uint32_t smb = smem_u32(sm);

    const int t = threadIdx.x, w = t >> 5, l = t & 31;
    const int s = blockIdx.y;
    const int b = blockIdx.z;
    const int n0 = blockIdx.x * 128;

    const uint4* Kg = (const uint4*)(g_Kh + (size_t)b * HW * CQD);
    const uint4* Qg = (const uint4*)(g_Qh + (size_t)b * HW * CQD);
    const uint4* Vg = (const uint4*)(g_Vh + (size_t)b * CCH * HW);

    if (t < 128) *(uint4*)(sm + SM_K + t * 16) = Kg[n0 + t];

    auto stage = [&](int buf, int m0) {
        const uint32_t vbase = smb + (buf ? SM_V1 : SM_V0);
#pragma unroll
        for (int jj = 0; jj < 4; jj++) {
            int i = t + jj * 256;
            int row = i >> 4, c16 = i & 15;
            cp16(vbase + row * VSTR + c16 * 16,
                 Vg + (size_t)row * (HW / 8) + (m0 >> 3) + c16);
        }
        if (t < 128) cp16(smb + (buf ? SM_Q1 : SM_Q0) + t * 16, Qg + m0 + t);
    };

    stage(0, s * NC * 128);
    CP_COMMIT();

    __syncthreads();
    uint32_t ka[2];
    ldsm2(ka, smb + SM_K + (16 * w + (l & 15)) * 16);

    float dacc[8][4];
#pragma unroll
    for (int ct = 0; ct < 8; ct++)
#pragma unroll
        for (int i = 0; i < 4; i++) dacc[ct][i] = 0.0f;

    for (int chunk = 0; chunk < NC; chunk++) {
        const int buf = chunk & 1;
        if (chunk + 1 < NC) {
            stage(buf ^ 1, (s * NC + chunk + 1) * 128);
            CP_COMMIT();
            CP_WAIT(1);
        } else {
            CP_WAIT(0);
        }
        __syncthreads();

        const uint32_t vbase = smb + (buf ? SM_V1 : SM_V0);
        const uint32_t qbase = smb + (buf ? SM_Q1 : SM_Q0);

        uint32_t pa[8][4];
#pragma unroll
        for (int half = 0; half < 2; half++) {
            uint32_t qb[8];
            ldsm4(qb + 0, qbase + (64 * half + l) * 16);
            ldsm4(qb + 4, qbase + (64 * half + 32 + l) * 16);
#pragma unroll
            for (int jj = 0; jj < 8; jj++) {
                float d0 = 0, d1 = 0, d2 = 0, d3 = 0;
                mma8(d0, d1, d2, d3, ka, qb[jj]);
                const int jt = 8 * half + jj;
                pa[jt >> 1][(jt & 1) * 2]     = h2ex2(cvt_h2(d0, d1));
                pa[jt >> 1][(jt & 1) * 2 + 1] = h2ex2(cvt_h2(d2, d3));
            }
        }

#pragma unroll
        for (int kk = 0; kk < 8; kk++) {
#pragma unroll
            for (int cp = 0; cp < 4; cp++) {
                uint32_t bb[4];
                ldsm4(bb, vbase
                          + (cp * 16 + ((l >> 4) << 3) + (l & 7)) * VSTR
                          + kk * 32 + ((l >> 3) & 1) * 16);
                mma16(dacc[2 * cp],     pa[kk], bb[0], bb[1]);
                mma16(dacc[2 * cp + 1], pa[kk], bb[2], bb[3]);
            }
        }
        __syncthreads();
    }

    float* sD = (float*)sm;
    const int r = l >> 2, q = l & 3;
#pragma unroll
    for (int ct = 0; ct < 8; ct++) {
        const int c = ct * 8 + 2 * q;
        sD[(16 * w + r) * OSTR + c]         = dacc[ct][0];
        sD[(16 * w + r) * OSTR + c + 1]     = dacc[ct][1];
        sD[(16 * w + r + 8) * OSTR + c]     = dacc[ct][2];
        sD[(16 * w + r + 8) * OSTR + c + 1] = dacc[ct][3];
    }
    __syncthreads();

    float* dst = g_Dp + (size_t)s * PSZ + (size_t)b * CCH * HW;
#pragma unroll
    for (int i = t; i < 128 * CCH; i += 256) {
        const int c = i >> 7, n = i & 127;
        dst[(size_t)c * HW + n0 + n] = sD[n * OSTR + c];
    }
}

// ---------------------------------------------------------------------------
// Kernel 5: combine split partials + gamma + residual (vectorized)
// ---------------------------------------------------------------------------
__global__ __launch_bounds__(256) void combine_kernel(
    const float* __restrict__ x,
    const float* __restrict__ gamma,
    float* __restrict__ out)
{
    const size_t i = ((size_t)blockIdx.x * 256 + threadIdx.x) * 4;
    const float gm = gamma[0] * (1.0f / 4096.0f);
    float4 a = *(const float4*)(g_Dp + i);
    float4 c = *(const float4*)(g_Dp + PSZ + i);
    float4 d = *(const float4*)(g_Dp + 2 * (size_t)PSZ + i);
    float4 e = *(const float4*)(g_Dp + 3 * (size_t)PSZ + i);
    float4 xv = *(const float4*)(x + i);
    float4 o;
    o.x = gm * ((a.x + c.x) + (d.x + e.x)) + xv.x;
    o.y = gm * ((a.y + c.y) + (d.y + e.y)) + xv.y;
    o.z = gm * ((a.z + c.z) + (d.z + e.z)) + xv.z;
    o.w = gm * ((a.w + c.w) + (d.w + e.w)) + xv.w;
    *(float4*)(out + i) = o;
}

// ---------------------------------------------------------------------------
extern "C" void kernel_launch(void* const* d_in, const int* in_sizes, int n_in,
                              void* d_out, int out_size)
{
    const float* x     = (const float*)d_in[0];
    const float* Wq    = (const float*)d_in[1];
    const float* bq    = (const float*)d_in[2];
    const float* Wk    = (const float*)d_in[3];
    const float* bk    = (const float*)d_in[4];
    const float* Wv    = (const float*)d_in[5];
    const float* bv    = (const float*)d_in[6];
    const float* gamma = (const float*)d_in[7];
    float* out = (float*)d_out;

    qkv_kernel<<<dim3(HW / 128, NBAT), 256>>>(x, Wq, bq, Wk, bk, Wv, bv);
    denom_kernel<<<dim3(HW / 128, NSPL, NBAT), 256>>>();
    vscale_kernel<<<dim3(HW / 512, NBAT), 256>>>();
    attn_kernel<<<dim3(HW / 128, NS, NBAT), 256>>>();
    combine_kernel<<<PSZ / 1024, 256>>>(x, gamma, out);
}

// round 11
// speedup vs baseline: 1.8161x; 1.0479x over previous
#include <cuda_runtime.h>
#include <cuda_fp16.h>
#include <cstdint>

// Problem constants
#define HW   4096
#define CCH  64
#define CQD  8
#define NBAT 4
#define NSPL 4          // denom j-split
#define NS   4          // attn key-split
#define NC   (HW / (NS * 128))   // chunks per attn block = 8
#define PSZ  (NBAT * CCH * HW)
#define L2E  1.4426950408889634f

// Scratch (device globals — no allocation allowed)
__device__ __half g_Qh[NBAT * HW * CQD];      // [b][m][8] fp16, pre-scaled by log2(e)
__device__ __half g_Kh[NBAT * HW * CQD];      // [b][n][8] fp16
__device__ __half g_Vh[NBAT * CCH * HW];      // [b][c][m] fp16 (vscale: *= 4096/denom[m])
__device__ float  g_dpart[NSPL * NBAT * HW];  // per-split softmax denominators
__device__ float  g_Dp[NS * PSZ];             // attn split partials [s][b][c][n]

// ---------------------------------------------------------------------------
// helpers
// ---------------------------------------------------------------------------
__device__ __forceinline__ uint32_t smem_u32(const void* p) {
    uint32_t a;
    asm("{ .reg .u64 t; cvta.to.shared.u64 t, %1; cvt.u32.u64 %0, t; }" : "=r"(a) : "l"(p));
    return a;
}
__device__ __forceinline__ void ldsm2(uint32_t* r, uint32_t addr) {
    asm volatile("ldmatrix.sync.aligned.m8n8.x2.shared.b16 {%0,%1}, [%2];"
                 : "=r"(r[0]), "=r"(r[1]) : "r"(addr));
}
__device__ __forceinline__ void ldsm4(uint32_t* r, uint32_t addr) {
    asm volatile("ldmatrix.sync.aligned.m8n8.x4.shared.b16 {%0,%1,%2,%3}, [%4];"
                 : "=r"(r[0]), "=r"(r[1]), "=r"(r[2]), "=r"(r[3]) : "r"(addr));
}
__device__ __forceinline__ void ldsm4t(uint32_t* r, uint32_t addr) {
    asm volatile("ldmatrix.sync.aligned.m8n8.x4.trans.shared.b16 {%0,%1,%2,%3}, [%4];"
                 : "=r"(r[0]), "=r"(r[1]), "=r"(r[2]), "=r"(r[3]) : "r"(addr));
}
// scores, f16 accumulate: D packed {(r,2q),(r,2q+1)} / {(r+8,..)} per reg
__device__ __forceinline__ void mma8h(uint32_t& c0, uint32_t& c1,
                                      const uint32_t* a, uint32_t b) {
    asm volatile("mma.sync.aligned.m16n8k8.row.col.f16.f16.f16.f16 "
                 "{%0,%1}, {%2,%3}, {%4}, {%5,%6};"
                 : "=r"(c0), "=r"(c1)
                 : "r"(a[0]), "r"(a[1]), "r"(b), "r"(0u), "r"(0u));
}
// P@V, f16 accumulate (2x HMMA rate vs f32-acc)
__device__ __forceinline__ void mma16h(uint32_t* d, const uint32_t* a,
                                       uint32_t b0, uint32_t b1) {
    asm volatile("mma.sync.aligned.m16n8k16.row.col.f16.f16.f16.f16 "
                 "{%0,%1}, {%2,%3,%4,%5}, {%6,%7}, {%0,%1};"
                 : "+r"(d[0]), "+r"(d[1])
                 : "r"(a[0]), "r"(a[1]), "r"(a[2]), "r"(a[3]), "r"(b0), "r"(b1));
}
// qkv GEMM keeps f32 accumulate
__device__ __forceinline__ void mma16(float* d, const uint32_t* a,
                                      uint32_t b0, uint32_t b1) {
    asm volatile("mma.sync.aligned.m16n8k16.row.col.f32.f16.f16.f32 "
                 "{%0,%1,%2,%3}, {%4,%5,%6,%7}, {%8,%9}, {%0,%1,%2,%3};"
                 : "+f"(d[0]), "+f"(d[1]), "+f"(d[2]), "+f"(d[3])
                 : "r"(a[0]), "r"(a[1]), "r"(a[2]), "r"(a[3]), "r"(b0), "r"(b1));
}
__device__ __forceinline__ uint32_t cvt_h2(float lo, float hi) {
    uint32_t r;
    asm("cvt.rn.f16x2.f32 %0, %1, %2;" : "=r"(r) : "f"(hi), "f"(lo));
    return r;
}
__device__ __forceinline__ uint32_t h2ex2(uint32_t a) {
    uint32_t r;
    asm("ex2.approx.f16x2 %0, %1;" : "=r"(r) : "r"(a));
    return r;
}
__device__ __forceinline__ uint32_t hadd2_(uint32_t a, uint32_t b) {
    uint32_t r;
    asm("add.f16x2 %0, %1, %2;" : "=r"(r) : "r"(a), "r"(b));
    return r;
}
__device__ __forceinline__ void cp16(uint32_t smem, const void* g) {
    asm volatile("cp.async.cg.shared.global [%0], [%1], 16;" :: "r"(smem), "l"(g));
}
#define CP_COMMIT() asm volatile("cp.async.commit_group;" ::: "memory")
#define CP_WAIT(n)  asm volatile("cp.async.wait_group %0;" :: "n"(n) : "memory")

// ---------------------------------------------------------------------------
// Kernel 1: QKV projections as a tensor-core GEMM (f32 acc).
// ---------------------------------------------------------------------------
#define XSTR  272
#define WSTR  144
#define SM_X  0
#define SM_W  17408
#define SM_BI 41472
#define SDSTR 81

__global__ __launch_bounds__(256) void qkv_kernel(
    const float* __restrict__ x,
    const float* __restrict__ Wq, const float* __restrict__ bq,
    const float* __restrict__ Wk, const float* __restrict__ bk,
    const float* __restrict__ Wv, const float* __restrict__ bv)
{
    __shared__ __align__(16) uint8_t sm[41792];
    const uint32_t smb = smem_u32(sm);

    const int t = threadIdx.x, w = t >> 5, l = t & 31;
    const int b = blockIdx.y;
    const int n0 = blockIdx.x * 128;

    float* bs = (float*)(sm + SM_BI);
    if (t < 80) {
        float v;
        if (t < 64)      v = bv[t];
        else if (t < 72) v = bq[t - 64] * L2E;
        else             v = bk[t - 72];
        bs[t] = v;
    }
#pragma unroll
    for (int idx = t; idx < 80 * 32; idx += 256) {
        const int o = idx >> 5, p = idx & 31;
        float lo, hi;
        if (o < 64)      { lo = Wv[o * 64 + 2 * p];          hi = Wv[o * 64 + 2 * p + 1]; }
        else if (o < 72) { lo = Wq[(o - 64) * 64 + 2 * p] * L2E;
                           hi = Wq[(o - 64) * 64 + 2 * p + 1] * L2E; }
        else             { lo = Wk[(o - 72) * 64 + 2 * p];   hi = Wk[(o - 72) * 64 + 2 * p + 1]; }
        *(uint32_t*)(sm + SM_W + o * WSTR + p * 4) = cvt_h2(lo, hi);
    }
    const float* xb = x + (size_t)b * CCH * HW + n0;
#pragma unroll
    for (int idx = t; idx < 64 * 64; idx += 256) {
        const int c = idx >> 6, p = idx & 63;
        float2 v = *(const float2*)(xb + (size_t)c * HW + 2 * p);
        *(uint32_t*)(sm + SM_X + c * XSTR + p * 4) = cvt_h2(v.x, v.y);
    }
    __syncthreads();

    float dacc[10][4];
#pragma unroll
    for (int ct = 0; ct < 10; ct++)
#pragma unroll
        for (int i = 0; i < 4; i++) dacc[ct][i] = 0.0f;

    const int nb = 16 * w;
#pragma unroll
    for (int ks = 0; ks < 4; ks++) {
        uint32_t a[4];
        ldsm4t(a, smb + SM_X
                  + ((l & 7) + ((l >> 4) & 1) * 8 + 16 * ks) * XSTR
                  + (nb + ((l >> 3) & 1) * 8) * 2);
#pragma unroll
        for (int ot = 0; ot < 5; ot++) {
            uint32_t bb[4];
            ldsm4(bb, smb + SM_W + (ot * 16 + ((l >> 4) << 3) + (l & 7)) * WSTR
                      + ks * 32 + ((l >> 3) & 1) * 16);
            mma16(dacc[2 * ot],     a, bb[0], bb[1]);
            mma16(dacc[2 * ot + 1], a, bb[2], bb[3]);
        }
    }

    __syncthreads();
    float* sD = (float*)sm;
    const int r = l >> 2, q = l & 3;
#pragma unroll
    for (int ct = 0; ct < 10; ct++) {
        const int c = ct * 8 + 2 * q;
        sD[(nb + r) * SDSTR + c]         = dacc[ct][0];
        sD[(nb + r) * SDSTR + c + 1]     = dacc[ct][1];
        sD[(nb + r + 8) * SDSTR + c]     = dacc[ct][2];
        sD[(nb + r + 8) * SDSTR + c + 1] = dacc[ct][3];
    }
    __syncthreads();

#pragma unroll
    for (int idx = t; idx < 64 * 64; idx += 256) {
        const int c = idx >> 6, p = idx & 63;
        const float bvv = bs[c];
        const float lo = sD[(2 * p) * SDSTR + c] + bvv;
        const float hi = sD[(2 * p + 1) * SDSTR + c] + bvv;
        *(uint32_t*)(g_Vh + ((size_t)b * CCH + c) * HW + n0 + 2 * p) = cvt_h2(lo, hi);
    }
    {
        const int n = t & 127;
        const int base = (t < 128) ? 64 : 72;
        __half* dst = (t < 128) ? g_Qh : g_Kh;
        uint32_t u[4];
#pragma unroll
        for (int jj = 0; jj < 4; jj++)
            u[jj] = cvt_h2(sD[n * SDSTR + base + 2 * jj] + bs[base + 2 * jj],
                           sD[n * SDSTR + base + 2 * jj + 1] + bs[base + 2 * jj + 1]);
        *(uint4*)(dst + ((size_t)b * HW + n0 + n) * CQD) = make_uint4(u[0], u[1], u[2], u[3]);
    }
}

// ---------------------------------------------------------------------------
// Kernel 2: softmax denominators via f16-acc MMA scores + f16x2 ex2.
// ---------------------------------------------------------------------------
__global__ __launch_bounds__(256) void denom_kernel()
{
    __shared__ __align__(16) uint8_t sm[4096];
    const uint32_t smb = smem_u32(sm);

    const int t = threadIdx.x, w = t >> 5, l = t & 31;
    const int b = blockIdx.z, s = blockIdx.y;
    const int mbase = blockIdx.x * 128;

    const uint4* Qg = (const uint4*)(g_Qh + (size_t)b * HW * CQD);
    const uint4* Kg = (const uint4*)(g_Kh + (size_t)b * HW * CQD);

    if (t < 128) *(uint4*)(sm + t * 16) = Qg[mbase + t];
    __syncthreads();
    uint32_t qa[2];
    ldsm2(qa, smb + (16 * w + (l & 15)) * 16);

    float rs0 = 0.0f, rs1 = 0.0f;
    for (int ch = 0; ch < (HW / NSPL) / 128; ch++) {
        const int nn0 = s * (HW / NSPL) + ch * 128;
        __syncthreads();
        if (t < 128) *(uint4*)(sm + 2048 + t * 16) = Kg[nn0 + t];
        __syncthreads();
        uint32_t kb[16];
        ldsm4(kb + 0,  smb + 2048 + l * 16);
        ldsm4(kb + 4,  smb + 2048 + (32 + l) * 16);
        ldsm4(kb + 8,  smb + 2048 + (64 + l) * 16);
        ldsm4(kb + 12, smb + 2048 + (96 + l) * 16);
        uint32_t a0 = 0u, a1 = 0u;
#pragma unroll
        for (int jj = 0; jj < 16; jj++) {
            uint32_t c0, c1;
            mma8h(c0, c1, qa, kb[jj]);
            a0 = hadd2_(a0, h2ex2(c0));
            a1 = hadd2_(a1, h2ex2(c1));
        }
        float2 f0 = __half22float2(*reinterpret_cast<__half2*>(&a0));
        float2 f1 = __half22float2(*reinterpret_cast<__half2*>(&a1));
        rs0 += f0.x + f0.y;
        rs1 += f1.x + f1.y;
    }
    rs0 += __shfl_xor_sync(0xFFFFFFFFu, rs0, 1);
    rs0 += __shfl_xor_sync(0xFFFFFFFFu, rs0, 2);
    rs1 += __shfl_xor_sync(0xFFFFFFFFu, rs1, 1);
    rs1 += __shfl_xor_sync(0xFFFFFFFFu, rs1, 2);
    if ((l & 3) == 0) {
        const int r = 16 * w + (l >> 2);
        float* dst = g_dpart + ((size_t)s * NBAT + b) * HW + mbase;
        dst[r]     = rs0;
        dst[r + 8] = rs1;
    }
}

// ---------------------------------------------------------------------------
// Kernel 3: prescale V in place (half2): V[c][m] *= 4096/denom[m]
// ---------------------------------------------------------------------------
__global__ __launch_bounds__(256) void vscale_kernel()
{
    const int t = threadIdx.x;
    const int b = blockIdx.y;
    const int m2 = blockIdx.x * 256 + t;
    const int m = 2 * m2;
    float da = g_dpart[(size_t)b * HW + m]
             + g_dpart[((size_t)NBAT + b) * HW + m]
             + g_dpart[((size_t)2 * NBAT + b) * HW + m]
             + g_dpart[((size_t)3 * NBAT + b) * HW + m];
    float db = g_dpart[(size_t)b * HW + m + 1]
             + g_dpart[((size_t)NBAT + b) * HW + m + 1]
             + g_dpart[((size_t)2 * NBAT + b) * HW + m + 1]
             + g_dpart[((size_t)3 * NBAT + b) * HW + m + 1];
    const __half2 inv = __floats2half2_rn(__fdividef(4096.0f, da),
                                          __fdividef(4096.0f, db));
    __half2* Vp = (__half2*)(g_Vh + (size_t)b * CCH * HW) + m2;
#pragma unroll
    for (int c = 0; c < CCH; c++)
        Vp[(size_t)c * (HW / 2)] = __hmul2(Vp[(size_t)c * (HW / 2)], inv);
}

// ---------------------------------------------------------------------------
// Kernel 4: attention aggregation — f16 accumulate, 4 blocks/SM (1 wave).
// ---------------------------------------------------------------------------
#define VSTR  272
#define SM_V0 0
#define SM_V1 17408
#define SM_Q0 34816
#define SM_Q1 36864
#define SM_K  38912
#define SMA_BYTES 40960
#define OSTR  65

__global__ __launch_bounds__(256, 4) void attn_kernel()
{
    __shared__ __align__(16) uint8_t sm[SMA_BYTES];
    const uint32_t smb = smem_u32(sm);

    const int t = threadIdx.x, w = t >> 5, l = t & 31;
    const int s = blockIdx.y;
    const int b = blockIdx.z;
    const int n0 = blockIdx.x * 128;

    const uint4* Kg = (const uint4*)(g_Kh + (size_t)b * HW * CQD);
    const uint4* Qg = (const uint4*)(g_Qh + (size_t)b * HW * CQD);
    const uint4* Vg = (const uint4*)(g_Vh + (size_t)b * CCH * HW);

    if (t < 128) *(uint4*)(sm + SM_K + t * 16) = Kg[n0 + t];

    auto stage = [&](int buf, int m0) {
        const uint32_t vbase = smb + (buf ? SM_V1 : SM_V0);
#pragma unroll
        for (int jj = 0; jj < 4; jj++) {
            int i = t + jj * 256;
            int row = i >> 4, c16 = i & 15;
            cp16(vbase + row * VSTR + c16 * 16,
                 Vg + (size_t)row * (HW / 8) + (m0 >> 3) + c16);
        }
        if (t < 128) cp16(smb + (buf ? SM_Q1 : SM_Q0) + t * 16, Qg + m0 + t);
    };

    stage(0, s * NC * 128);
    CP_COMMIT();

    __syncthreads();
    uint32_t ka[2];
    ldsm2(ka, smb + SM_K + (16 * w + (l & 15)) * 16);

    uint32_t dacc[8][2];            // f16x2 accumulators
#pragma unroll
    for (int ct = 0; ct < 8; ct++) { dacc[ct][0] = 0u; dacc[ct][1] = 0u; }

    for (int chunk = 0; chunk < NC; chunk++) {
        const int buf = chunk & 1;
        if (chunk + 1 < NC) {
            stage(buf ^ 1, (s * NC + chunk + 1) * 128);
            CP_COMMIT();
            CP_WAIT(1);
        } else {
            CP_WAIT(0);
        }
        __syncthreads();

        const uint32_t vbase = smb + (buf ? SM_V1 : SM_V0);
        const uint32_t qbase = smb + (buf ? SM_Q1 : SM_Q0);

        // ---- scores (f16 acc) -> ex2 -> P A-frags, no cvt needed ----
        uint32_t pa[8][4];
#pragma unroll
        for (int half = 0; half < 2; half++) {
            uint32_t qb[8];
            ldsm4(qb + 0, qbase + (64 * half + l) * 16);
            ldsm4(qb + 4, qbase + (64 * half + 32 + l) * 16);
#pragma unroll
            for (int jj = 0; jj < 8; jj++) {
                uint32_t c0, c1;
                mma8h(c0, c1, ka, qb[jj]);
                const int jt = 8 * half + jj;
                pa[jt >> 1][(jt & 1) * 2]     = h2ex2(c0);
                pa[jt >> 1][(jt & 1) * 2 + 1] = h2ex2(c1);
            }
        }

        // ---- D += P @ V' (f16 acc, 2x rate) ----
#pragma unroll
        for (int kk = 0; kk < 8; kk++) {
#pragma unroll
            for (int cp = 0; cp < 4; cp++) {
                uint32_t bb[4];
                ldsm4(bb, vbase
                          + (cp * 16 + ((l >> 4) << 3) + (l & 7)) * VSTR
                          + kk * 32 + ((l >> 3) & 1) * 16);
                mma16h(dacc[2 * cp],     pa[kk], bb[0], bb[1]);
                mma16h(dacc[2 * cp + 1], pa[kk], bb[2], bb[3]);
            }
        }
        __syncthreads();
    }

    // ---- unpack f16 accumulators -> sD -> coalesced [s][b][c][n] writes ----
    float* sD = (float*)sm;
    const int r = l >> 2, q = l & 3;
#pragma unroll
    for (int ct = 0; ct < 8; ct++) {
        const int c = ct * 8 + 2 * q;
        float2 lo = __half22float2(*reinterpret_cast<__half2*>(&dacc[ct][0]));
        float2 hi = __half22float2(*reinterpret_cast<__half2*>(&dacc[ct][1]));
        sD[(16 * w + r) * OSTR + c]         = lo.x;
        sD[(16 * w + r) * OSTR + c + 1]     = lo.y;
        sD[(16 * w + r + 8) * OSTR + c]     = hi.x;
        sD[(16 * w + r + 8) * OSTR + c + 1] = hi.y;
    }
    __syncthreads();

    float* dst = g_Dp + (size_t)s * PSZ + (size_t)b * CCH * HW;
#pragma unroll
    for (int i = t; i < 128 * CCH; i += 256) {
        const int c = i >> 7, n = i & 127;
        dst[(size_t)c * HW + n0 + n] = sD[n * OSTR + c];
    }
}

// ---------------------------------------------------------------------------
// Kernel 5: combine split partials + gamma + residual (vectorized)
// ---------------------------------------------------------------------------
__global__ __launch_bounds__(256) void combine_kernel(
    const float* __restrict__ x,
    const float* __restrict__ gamma,
    float* __restrict__ out)
{
    const size_t i = ((size_t)blockIdx.x * 256 + threadIdx.x) * 4;
    const float gm = gamma[0] * (1.0f / 4096.0f);
    float4 a = *(const float4*)(g_Dp + i);
    float4 c = *(const float4*)(g_Dp + PSZ + i);
    float4 d = *(const float4*)(g_Dp + 2 * (size_t)PSZ + i);
    float4 e = *(const float4*)(g_Dp + 3 * (size_t)PSZ + i);
    float4 xv = *(const float4*)(x + i);
    float4 o;
    o.x = gm * ((a.x + c.x) + (d.x + e.x)) + xv.x;
    o.y = gm * ((a.y + c.y) + (d.y + e.y)) + xv.y;
    o.z = gm * ((a.z + c.z) + (d.z + e.z)) + xv.z;
    o.w = gm * ((a.w + c.w) + (d.w + e.w)) + xv.w;
    *(float4*)(out + i) = o;
}

// ---------------------------------------------------------------------------
extern "C" void kernel_launch(void* const* d_in, const int* in_sizes, int n_in,
                              void* d_out, int out_size)
{
    const float* x     = (const float*)d_in[0];
    const float* Wq    = (const float*)d_in[1];
    const float* bq    = (const float*)d_in[2];
    const float* Wk    = (const float*)d_in[3];
    const float* bk    = (const float*)d_in[4];
    const float* Wv    = (const float*)d_in[5];
    const float* bv    = (const float*)d_in[6];
    const float* gamma = (const float*)d_in[7];
    float* out = (float*)d_out;

    qkv_kernel<<<dim3(HW / 128, NBAT), 256>>>(x, Wq, bq, Wk, bk, Wv, bv);
    denom_kernel<<<dim3(HW / 128, NSPL, NBAT), 256>>>();
    vscale_kernel<<<dim3(HW / 512, NBAT), 256>>>();
    attn_kernel<<<dim3(HW / 128, NS, NBAT), 256>>>();
    combine_kernel<<<PSZ / 1024, 256>>>(x, gamma, out);
}

// round 12
// speedup vs baseline: 1.8681x; 1.0287x over previous
#include <cuda_runtime.h>
#include <cuda_fp16.h>
#include <cstdint>

// Problem constants
#define HW   4096
#define CCH  64
#define CQD  8
#define NBAT 4
#define NSPL 4          // denom j-split
#define NS   4          // attn key-split
#define NC   (HW / (NS * 128))   // chunks per attn block = 8
#define PSZ  (NBAT * CCH * HW)
#define L2E  1.4426950408889634f

// Scratch (device globals — no allocation allowed)
__device__ __half g_Qh[NBAT * HW * CQD];      // [b][m][8] fp16, pre-scaled by log2(e)
__device__ __half g_Kh[NBAT * HW * CQD];      // [b][n][8] fp16
__device__ __half g_Vh[NBAT * CCH * HW];      // [b][c][m] fp16 (vscale: *= 4096/denom[m])
__device__ float  g_dpart[NSPL * NBAT * HW];  // per-split softmax denominators
__device__ float  g_Dp[NS * PSZ];             // attn split partials [s][b][c][n]

// ---------------------------------------------------------------------------
// helpers
// ---------------------------------------------------------------------------
__device__ __forceinline__ uint32_t smem_u32(const void* p) {
    uint32_t a;
    asm("{ .reg .u64 t; cvta.to.shared.u64 t, %1; cvt.u32.u64 %0, t; }" : "=r"(a) : "l"(p));
    return a;
}
__device__ __forceinline__ void ldsm2(uint32_t* r, uint32_t addr) {
    asm volatile("ldmatrix.sync.aligned.m8n8.x2.shared.b16 {%0,%1}, [%2];"
                 : "=r"(r[0]), "=r"(r[1]) : "r"(addr));
}
__device__ __forceinline__ void ldsm4(uint32_t* r, uint32_t addr) {
    asm volatile("ldmatrix.sync.aligned.m8n8.x4.shared.b16 {%0,%1,%2,%3}, [%4];"
                 : "=r"(r[0]), "=r"(r[1]), "=r"(r[2]), "=r"(r[3]) : "r"(addr));
}
__device__ __forceinline__ void ldsm4t(uint32_t* r, uint32_t addr) {
    asm volatile("ldmatrix.sync.aligned.m8n8.x4.trans.shared.b16 {%0,%1,%2,%3}, [%4];"
                 : "=r"(r[0]), "=r"(r[1]), "=r"(r[2]), "=r"(r[3]) : "r"(addr));
}
// scores, f16 accumulate
__device__ __forceinline__ void mma8h(uint32_t& c0, uint32_t& c1,
                                      const uint32_t* a, uint32_t b) {
    asm volatile("mma.sync.aligned.m16n8k8.row.col.f16.f16.f16.f16 "
                 "{%0,%1}, {%2,%3}, {%4}, {%5,%6};"
                 : "=r"(c0), "=r"(c1)
                 : "r"(a[0]), "r"(a[1]), "r"(b), "r"(0u), "r"(0u));
}
// P@V, f16 accumulate
__device__ __forceinline__ void mma16h(uint32_t* d, const uint32_t* a,
                                       uint32_t b0, uint32_t b1) {
    asm volatile("mma.sync.aligned.m16n8k16.row.col.f16.f16.f16.f16 "
                 "{%0,%1}, {%2,%3,%4,%5}, {%6,%7}, {%0,%1};"
                 : "+r"(d[0]), "+r"(d[1])
                 : "r"(a[0]), "r"(a[1]), "r"(a[2]), "r"(a[3]), "r"(b0), "r"(b1));
}
// qkv GEMM keeps f32 accumulate
__device__ __forceinline__ void mma16(float* d, const uint32_t* a,
                                      uint32_t b0, uint32_t b1) {
    asm volatile("mma.sync.aligned.m16n8k16.row.col.f32.f16.f16.f32 "
                 "{%0,%1,%2,%3}, {%4,%5,%6,%7}, {%8,%9}, {%0,%1,%2,%3};"
                 : "+f"(d[0]), "+f"(d[1]), "+f"(d[2]), "+f"(d[3])
                 : "r"(a[0]), "r"(a[1]), "r"(a[2]), "r"(a[3]), "r"(b0), "r"(b1));
}
__device__ __forceinline__ uint32_t cvt_h2(float lo, float hi) {
    uint32_t r;
    asm("cvt.rn.f16x2.f32 %0, %1, %2;" : "=r"(r) : "f"(hi), "f"(lo));
    return r;
}
__device__ __forceinline__ uint32_t h2ex2(uint32_t a) {
    uint32_t r;
    asm("ex2.approx.f16x2 %0, %1;" : "=r"(r) : "r"(a));
    return r;
}
__device__ __forceinline__ uint32_t hadd2_(uint32_t a, uint32_t b) {
    uint32_t r;
    asm("add.f16x2 %0, %1, %2;" : "=r"(r) : "r"(a), "r"(b));
    return r;
}
__device__ __forceinline__ void cp16(uint32_t smem, const void* g) {
    asm volatile("cp.async.cg.shared.global [%0], [%1], 16;" :: "r"(smem), "l"(g));
}
#define CP_COMMIT() asm volatile("cp.async.commit_group;" ::: "memory")
#define CP_WAIT(n)  asm volatile("cp.async.wait_group %0;" :: "n"(n) : "memory")

// ---------------------------------------------------------------------------
// Kernel 1: QKV projections as a tensor-core GEMM (f32 acc).
// ---------------------------------------------------------------------------
#define XSTR  272
#define WSTR  144
#define SM_X  0
#define SM_W  17408
#define SM_BI 41472
#define SDSTR 81

__global__ __launch_bounds__(256) void qkv_kernel(
    const float* __restrict__ x,
    const float* __restrict__ Wq, const float* __restrict__ bq,
    const float* __restrict__ Wk, const float* __restrict__ bk,
    const float* __restrict__ Wv, const float* __restrict__ bv)
{
    __shared__ __align__(16) uint8_t sm[41792];
    const uint32_t smb = smem_u32(sm);

    const int t = threadIdx.x, w = t >> 5, l = t & 31;
    const int b = blockIdx.y;
    const int n0 = blockIdx.x * 128;

    float* bs = (float*)(sm + SM_BI);
    if (t < 80) {
        float v;
        if (t < 64)      v = bv[t];
        else if (t < 72) v = bq[t - 64] * L2E;
        else             v = bk[t - 72];
        bs[t] = v;
    }
#pragma unroll
    for (int idx = t; idx < 80 * 32; idx += 256) {
        const int o = idx >> 5, p = idx & 31;
        float lo, hi;
        if (o < 64)      { lo = Wv[o * 64 + 2 * p];          hi = Wv[o * 64 + 2 * p + 1]; }
        else if (o < 72) { lo = Wq[(o - 64) * 64 + 2 * p] * L2E;
                           hi = Wq[(o - 64) * 64 + 2 * p + 1] * L2E; }
        else             { lo = Wk[(o - 72) * 64 + 2 * p];   hi = Wk[(o - 72) * 64 + 2 * p + 1]; }
        *(uint32_t*)(sm + SM_W + o * WSTR + p * 4) = cvt_h2(lo, hi);
    }
    const float* xb = x + (size_t)b * CCH * HW + n0;
#pragma unroll
    for (int idx = t; idx < 64 * 64; idx += 256) {
        const int c = idx >> 6, p = idx & 63;
        float2 v = *(const float2*)(xb + (size_t)c * HW + 2 * p);
        *(uint32_t*)(sm + SM_X + c * XSTR + p * 4) = cvt_h2(v.x, v.y);
    }
    __syncthreads();

    float dacc[10][4];
#pragma unroll
    for (int ct = 0; ct < 10; ct++)
#pragma unroll
        for (int i = 0; i < 4; i++) dacc[ct][i] = 0.0f;

    const int nb = 16 * w;
#pragma unroll
    for (int ks = 0; ks < 4; ks++) {
        uint32_t a[4];
        ldsm4t(a, smb + SM_X
                  + ((l & 7) + ((l >> 4) & 1) * 8 + 16 * ks) * XSTR
                  + (nb + ((l >> 3) & 1) * 8) * 2);
#pragma unroll
        for (int ot = 0; ot < 5; ot++) {
            uint32_t bb[4];
            ldsm4(bb, smb + SM_W + (ot * 16 + ((l >> 4) << 3) + (l & 7)) * WSTR
                      + ks * 32 + ((l >> 3) & 1) * 16);
            mma16(dacc[2 * ot],     a, bb[0], bb[1]);
            mma16(dacc[2 * ot + 1], a, bb[2], bb[3]);
        }
    }

    __syncthreads();
    float* sD = (float*)sm;
    const int r = l >> 2, q = l & 3;
#pragma unroll
    for (int ct = 0; ct < 10; ct++) {
        const int c = ct * 8 + 2 * q;
        sD[(nb + r) * SDSTR + c]         = dacc[ct][0];
        sD[(nb + r) * SDSTR + c + 1]     = dacc[ct][1];
        sD[(nb + r + 8) * SDSTR + c]     = dacc[ct][2];
        sD[(nb + r + 8) * SDSTR + c + 1] = dacc[ct][3];
    }
    __syncthreads();

#pragma unroll
    for (int idx = t; idx < 64 * 64; idx += 256) {
        const int c = idx >> 6, p = idx & 63;
        const float bvv = bs[c];
        const float lo = sD[(2 * p) * SDSTR + c] + bvv;
        const float hi = sD[(2 * p + 1) * SDSTR + c] + bvv;
        *(uint32_t*)(g_Vh + ((size_t)b * CCH + c) * HW + n0 + 2 * p) = cvt_h2(lo, hi);
    }
    {
        const int n = t & 127;
        const int base = (t < 128) ? 64 : 72;
        __half* dst = (t < 128) ? g_Qh : g_Kh;
        uint32_t u[4];
#pragma unroll
        for (int jj = 0; jj < 4; jj++)
            u[jj] = cvt_h2(sD[n * SDSTR + base + 2 * jj] + bs[base + 2 * jj],
                           sD[n * SDSTR + base + 2 * jj + 1] + bs[base + 2 * jj + 1]);
        *(uint4*)(dst + ((size_t)b * HW + n0 + n) * CQD) = make_uint4(u[0], u[1], u[2], u[3]);
    }
}

// ---------------------------------------------------------------------------
// Kernel 2: softmax denominators via f16-acc MMA scores + f16x2 ex2.
// ---------------------------------------------------------------------------
__global__ __launch_bounds__(256) void denom_kernel()
{
    __shared__ __align__(16) uint8_t sm[4096];
    const uint32_t smb = smem_u32(sm);

    const int t = threadIdx.x, w = t >> 5, l = t & 31;
    const int b = blockIdx.z, s = blockIdx.y;
    const int mbase = blockIdx.x * 128;

    const uint4* Qg = (const uint4*)(g_Qh + (size_t)b * HW * CQD);
    const uint4* Kg = (const uint4*)(g_Kh + (size_t)b * HW * CQD);

    if (t < 128) *(uint4*)(sm + t * 16) = Qg[mbase + t];
    __syncthreads();
    uint32_t qa[2];
    ldsm2(qa, smb + (16 * w + (l & 15)) * 16);

    float rs0 = 0.0f, rs1 = 0.0f;
    for (int ch = 0; ch < (HW / NSPL) / 128; ch++) {
        const int nn0 = s * (HW / NSPL) + ch * 128;
        __syncthreads();
        if (t < 128) *(uint4*)(sm + 2048 + t * 16) = Kg[nn0 + t];
        __syncthreads();
        uint32_t kb[16];
        ldsm4(kb + 0,  smb + 2048 + l * 16);
        ldsm4(kb + 4,  smb + 2048 + (32 + l) * 16);
        ldsm4(kb + 8,  smb + 2048 + (64 + l) * 16);
        ldsm4(kb + 12, smb + 2048 + (96 + l) * 16);
        uint32_t a0 = 0u, a1 = 0u;
#pragma unroll
        for (int jj = 0; jj < 16; jj++) {
            uint32_t c0, c1;
            mma8h(c0, c1, qa, kb[jj]);
            a0 = hadd2_(a0, h2ex2(c0));
            a1 = hadd2_(a1, h2ex2(c1));
        }
        float2 f0 = __half22float2(*reinterpret_cast<__half2*>(&a0));
        float2 f1 = __half22float2(*reinterpret_cast<__half2*>(&a1));
        rs0 += f0.x + f0.y;
        rs1 += f1.x + f1.y;
    }
    rs0 += __shfl_xor_sync(0xFFFFFFFFu, rs0, 1);
    rs0 += __shfl_xor_sync(0xFFFFFFFFu, rs0, 2);
    rs1 += __shfl_xor_sync(0xFFFFFFFFu, rs1, 1);
    rs1 += __shfl_xor_sync(0xFFFFFFFFu, rs1, 2);
    if ((l & 3) == 0) {
        const int r = 16 * w + (l >> 2);
        float* dst = g_dpart + ((size_t)s * NBAT + b) * HW + mbase;
        dst[r]     = rs0;
        dst[r + 8] = rs1;
    }
}

// ---------------------------------------------------------------------------
// Kernel 3: prescale V in place (half2): V[c][m] *= 4096/denom[m]
// ---------------------------------------------------------------------------
__global__ __launch_bounds__(256) void vscale_kernel()
{
    const int t = threadIdx.x;
    const int b = blockIdx.y;
    const int m2 = blockIdx.x * 256 + t;
    const int m = 2 * m2;
    float da = g_dpart[(size_t)b * HW + m]
             + g_dpart[((size_t)NBAT + b) * HW + m]
             + g_dpart[((size_t)2 * NBAT + b) * HW + m]
             + g_dpart[((size_t)3 * NBAT + b) * HW + m];
    float db = g_dpart[(size_t)b * HW + m + 1]
             + g_dpart[((size_t)NBAT + b) * HW + m + 1]
             + g_dpart[((size_t)2 * NBAT + b) * HW + m + 1]
             + g_dpart[((size_t)3 * NBAT + b) * HW + m + 1];
    const __half2 inv = __floats2half2_rn(__fdividef(4096.0f, da),
                                          __fdividef(4096.0f, db));
    __half2* Vp = (__half2*)(g_Vh + (size_t)b * CCH * HW) + m2;
#pragma unroll
    for (int c = 0; c < CCH; c++)
        Vp[(size_t)c * (HW / 2)] = __hmul2(Vp[(size_t)c * (HW / 2)], inv);
}

// ---------------------------------------------------------------------------
// Kernel 4: attention aggregation — 4 warps x 32 pixel rows (2x M-tile).
//   Both 16-row A-groups of a warp share every V ldsm4 and Q B-frag,
//   halving smem crossbar traffic per pixel (the measured bottleneck).
// ---------------------------------------------------------------------------
#define VSTR  272
#define SM_V0 0
#define SM_V1 17408
#define SM_Q0 34816
#define SM_Q1 36864
#define SM_K  38912
#define SMA_BYTES 40960
#define OSTR  65

__global__ __launch_bounds__(128, 4) void attn_kernel()
{
    __shared__ __align__(16) uint8_t sm[SMA_BYTES];
    const uint32_t smb = smem_u32(sm);

    const int t = threadIdx.x, w = t >> 5, l = t & 31;
    const int s = blockIdx.y;
    const int b = blockIdx.z;
    const int n0 = blockIdx.x * 128;

    const uint4* Kg = (const uint4*)(g_Kh + (size_t)b * HW * CQD);
    const uint4* Qg = (const uint4*)(g_Qh + (size_t)b * HW * CQD);
    const uint4* Vg = (const uint4*)(g_Vh + (size_t)b * CCH * HW);

    *(uint4*)(sm + SM_K + t * 16) = Kg[n0 + t];

    auto stage = [&](int buf, int m0) {
        const uint32_t vbase = smb + (buf ? SM_V1 : SM_V0);
#pragma unroll
        for (int jj = 0; jj < 8; jj++) {
            int i = t + jj * 128;
            int row = i >> 4, c16 = i & 15;
            cp16(vbase + row * VSTR + c16 * 16,
                 Vg + (size_t)row * (HW / 8) + (m0 >> 3) + c16);
        }
        cp16(smb + (buf ? SM_Q1 : SM_Q0) + t * 16, Qg + m0 + t);
    };

    stage(0, s * NC * 128);
    CP_COMMIT();

    __syncthreads();
    // warp w owns pixel rows 32w..32w+31: two 16-row A-frag groups
    uint32_t kaA[2], kaB[2];
    ldsm2(kaA, smb + SM_K + (32 * w + (l & 15)) * 16);
    ldsm2(kaB, smb + SM_K + (32 * w + 16 + (l & 15)) * 16);

    uint32_t daccA[8][2], daccB[8][2];
#pragma unroll
    for (int ct = 0; ct < 8; ct++) {
        daccA[ct][0] = daccA[ct][1] = 0u;
        daccB[ct][0] = daccB[ct][1] = 0u;
    }

    for (int chunk = 0; chunk < NC; chunk++) {
        const int buf = chunk & 1;
        if (chunk + 1 < NC) {
            stage(buf ^ 1, (s * NC + chunk + 1) * 128);
            CP_COMMIT();
            CP_WAIT(1);
        } else {
            CP_WAIT(0);
        }
        __syncthreads();

        const uint32_t vbase = smb + (buf ? SM_V1 : SM_V0);
        const uint32_t qbase = smb + (buf ? SM_Q1 : SM_Q0);

        // ---- scores (f16 acc) for both row groups; qb shared ----
        uint32_t paA[8][4], paB[8][4];
#pragma unroll
        for (int half = 0; half < 2; half++) {
            uint32_t qb[8];
            ldsm4(qb + 0, qbase + (64 * half + l) * 16);
            ldsm4(qb + 4, qbase + (64 * half + 32 + l) * 16);
#pragma unroll
            for (int jj = 0; jj < 8; jj++) {
                const int jt = 8 * half + jj;
                uint32_t c0, c1;
                mma8h(c0, c1, kaA, qb[jj]);
                paA[jt >> 1][(jt & 1) * 2]     = h2ex2(c0);
                paA[jt >> 1][(jt & 1) * 2 + 1] = h2ex2(c1);
                mma8h(c0, c1, kaB, qb[jj]);
                paB[jt >> 1][(jt & 1) * 2]     = h2ex2(c0);
                paB[jt >> 1][(jt & 1) * 2 + 1] = h2ex2(c1);
            }
        }

        // ---- D += P @ V'; every V ldsm4 feeds both row groups ----
#pragma unroll
        for (int kk = 0; kk < 8; kk++) {
#pragma unroll
            for (int cp = 0; cp < 4; cp++) {
                uint32_t bb[4];
                ldsm4(bb, vbase
                          + (cp * 16 + ((l >> 4) << 3) + (l & 7)) * VSTR
                          + kk * 32 + ((l >> 3) & 1) * 16);
                mma16h(daccA[2 * cp],     paA[kk], bb[0], bb[1]);
                mma16h(daccA[2 * cp + 1], paA[kk], bb[2], bb[3]);
                mma16h(daccB[2 * cp],     paB[kk], bb[0], bb[1]);
                mma16h(daccB[2 * cp + 1], paB[kk], bb[2], bb[3]);
            }
        }
        __syncthreads();
    }

    // ---- unpack f16 accumulators -> sD -> coalesced [s][b][c][n] writes ----
    float* sD = (float*)sm;
    const int r = l >> 2, q = l & 3;
#pragma unroll
    for (int ct = 0; ct < 8; ct++) {
        const int c = ct * 8 + 2 * q;
        float2 lo = __half22float2(*reinterpret_cast<__half2*>(&daccA[ct][0]));
        float2 hi = __half22float2(*reinterpret_cast<__half2*>(&daccA[ct][1]));
        sD[(32 * w + r) * OSTR + c]          = lo.x;
        sD[(32 * w + r) * OSTR + c + 1]      = lo.y;
        sD[(32 * w + r + 8) * OSTR + c]      = hi.x;
        sD[(32 * w + r + 8) * OSTR + c + 1]  = hi.y;
        lo = __half22float2(*reinterpret_cast<__half2*>(&daccB[ct][0]));
        hi = __half22float2(*reinterpret_cast<__half2*>(&daccB[ct][1]));
        sD[(32 * w + 16 + r) * OSTR + c]         = lo.x;
        sD[(32 * w + 16 + r) * OSTR + c + 1]     = lo.y;
        sD[(32 * w + 24 + r) * OSTR + c]         = hi.x;
        sD[(32 * w + 24 + r) * OSTR + c + 1]     = hi.y;
    }
    __syncthreads();

    float* dst = g_Dp + (size_t)s * PSZ + (size_t)b * CCH * HW;
#pragma unroll
    for (int i = t; i < 128 * CCH; i += 128) {
        const int c = i >> 7, n = i & 127;
        dst[(size_t)c * HW + n0 + n] = sD[n * OSTR + c];
    }
}

// ---------------------------------------------------------------------------
// Kernel 5: combine split partials + gamma + residual (vectorized)
// ---------------------------------------------------------------------------
__global__ __launch_bounds__(256) void combine_kernel(
    const float* __restrict__ x,
    const float* __restrict__ gamma,
    float* __restrict__ out)
{
    const size_t i = ((size_t)blockIdx.x * 256 + threadIdx.x) * 4;
    const float gm = gamma[0] * (1.0f / 4096.0f);
    float4 a = *(const float4*)(g_Dp + i);
    float4 c = *(const float4*)(g_Dp + PSZ + i);
    float4 d = *(const float4*)(g_Dp + 2 * (size_t)PSZ + i);
    float4 e = *(const float4*)(g_Dp + 3 * (size_t)PSZ + i);
    float4 xv = *(const float4*)(x + i);
    float4 o;
    o.x = gm * ((a.x + c.x) + (d.x + e.x)) + xv.x;
    o.y = gm * ((a.y + c.y) + (d.y + e.y)) + xv.y;
    o.z = gm * ((a.z + c.z) + (d.z + e.z)) + xv.z;
    o.w = gm * ((a.w + c.w) + (d.w + e.w)) + xv.w;
    *(float4*)(out + i) = o;
}

// ---------------------------------------------------------------------------
extern "C" void kernel_launch(void* const* d_in, const int* in_sizes, int n_in,
                              void* d_out, int out_size)
{
    const float* x     = (const float*)d_in[0];
    const float* Wq    = (const float*)d_in[1];
    const float* bq    = (const float*)d_in[2];
    const float* Wk    = (const float*)d_in[3];
    const float* bk    = (const float*)d_in[4];
    const float* Wv    = (const float*)d_in[5];
    const float* bv    = (const float*)d_in[6];
    const float* gamma = (const float*)d_in[7];
    float* out = (float*)d_out;

    qkv_kernel<<<dim3(HW / 128, NBAT), 256>>>(x, Wq, bq, Wk, bk, Wv, bv);
    denom_kernel<<<dim3(HW / 128, NSPL, NBAT), 256>>>();
    vscale_kernel<<<dim3(HW / 512, NBAT), 256>>>();
    attn_kernel<<<dim3(HW / 128, NS, NBAT), 128>>>();
    combine_kernel<<<PSZ / 1024, 256>>>(x, gamma, out);
}

// round 13
// speedup vs baseline: 1.9312x; 1.0338x over previous
#include <cuda_runtime.h>
#include <cuda_fp16.h>
#include <cstdint>

// Problem constants
#define HW   4096
#define CCH  64
#define CQD  8
#define NBAT 4
#define NSPL 4          // denom j-split
#define NS   8          // attn key-split (raised for occupancy)
#define NC   (HW / (NS * 128))   // chunks per attn block = 4
#define PSZ  (NBAT * CCH * HW)
#define L2E  1.4426950408889634f

// Scratch (device globals — no allocation allowed)
__device__ __half g_Qh[NBAT * HW * CQD];      // [b][m][8] fp16, pre-scaled by log2(e)
__device__ __half g_Kh[NBAT * HW * CQD];      // [b][n][8] fp16
__device__ __half g_Vh[NBAT * CCH * HW];      // [b][c][m] fp16 (vscale: *= 4096/denom[m])
__device__ float  g_dpart[NSPL * NBAT * HW];  // per-split softmax denominators
__device__ float  g_Dp[NS * PSZ];             // attn split partials [s][b][c][n]

// ---------------------------------------------------------------------------
// helpers
// ---------------------------------------------------------------------------
__device__ __forceinline__ uint32_t smem_u32(const void* p) {
    uint32_t a;
    asm("{ .reg .u64 t; cvta.to.shared.u64 t, %1; cvt.u32.u64 %0, t; }" : "=r"(a) : "l"(p));
    return a;
}
__device__ __forceinline__ void ldsm2(uint32_t* r, uint32_t addr) {
    asm volatile("ldmatrix.sync.aligned.m8n8.x2.shared.b16 {%0,%1}, [%2];"
                 : "=r"(r[0]), "=r"(r[1]) : "r"(addr));
}
__device__ __forceinline__ void ldsm4(uint32_t* r, uint32_t addr) {
    asm volatile("ldmatrix.sync.aligned.m8n8.x4.shared.b16 {%0,%1,%2,%3}, [%4];"
                 : "=r"(r[0]), "=r"(r[1]), "=r"(r[2]), "=r"(r[3]) : "r"(addr));
}
__device__ __forceinline__ void ldsm4t(uint32_t* r, uint32_t addr) {
    asm volatile("ldmatrix.sync.aligned.m8n8.x4.trans.shared.b16 {%0,%1,%2,%3}, [%4];"
                 : "=r"(r[0]), "=r"(r[1]), "=r"(r[2]), "=r"(r[3]) : "r"(addr));
}
// scores, f16 accumulate
__device__ __forceinline__ void mma8h(uint32_t& c0, uint32_t& c1,
                                      const uint32_t* a, uint32_t b) {
    asm volatile("mma.sync.aligned.m16n8k8.row.col.f16.f16.f16.f16 "
                 "{%0,%1}, {%2,%3}, {%4}, {%5,%6};"
                 : "=r"(c0), "=r"(c1)
                 : "r"(a[0]), "r"(a[1]), "r"(b), "r"(0u), "r"(0u));
}
// P@V, f16 accumulate
__device__ __forceinline__ void mma16h(uint32_t* d, const uint32_t* a,
                                       uint32_t b0, uint32_t b1) {
    asm volatile("mma.sync.aligned.m16n8k16.row.col.f16.f16.f16.f16 "
                 "{%0,%1}, {%2,%3,%4,%5}, {%6,%7}, {%0,%1};"
                 : "+r"(d[0]), "+r"(d[1])
                 : "r"(a[0]), "r"(a[1]), "r"(a[2]), "r"(a[3]), "r"(b0), "r"(b1));
}
// qkv GEMM keeps f32 accumulate
__device__ __forceinline__ void mma16(float* d, const uint32_t* a,
                                      uint32_t b0, uint32_t b1) {
    asm volatile("mma.sync.aligned.m16n8k16.row.col.f32.f16.f16.f32 "
                 "{%0,%1,%2,%3}, {%4,%5,%6,%7}, {%8,%9}, {%0,%1,%2,%3};"
                 : "+f"(d[0]), "+f"(d[1]), "+f"(d[2]), "+f"(d[3])
                 : "r"(a[0]), "r"(a[1]), "r"(a[2]), "r"(a[3]), "r"(b0), "r"(b1));
}
__device__ __forceinline__ uint32_t cvt_h2(float lo, float hi) {
    uint32_t r;
    asm("cvt.rn.f16x2.f32 %0, %1, %2;" : "=r"(r) : "f"(hi), "f"(lo));
    return r;
}
__device__ __forceinline__ uint32_t h2ex2(uint32_t a) {
    uint32_t r;
    asm("ex2.approx.f16x2 %0, %1;" : "=r"(r) : "r"(a));
    return r;
}
__device__ __forceinline__ uint32_t hadd2_(uint32_t a, uint32_t b) {
    uint32_t r;
    asm("add.f16x2 %0, %1, %2;" : "=r"(r) : "r"(a), "r"(b));
    return r;
}
__device__ __forceinline__ void cp16(uint32_t smem, const void* g) {
    asm volatile("cp.async.cg.shared.global [%0], [%1], 16;" :: "r"(smem), "l"(g));
}
#define CP_COMMIT() asm volatile("cp.async.commit_group;" ::: "memory")
#define CP_WAIT(n)  asm volatile("cp.async.wait_group %0;" :: "n"(n) : "memory")

// ---------------------------------------------------------------------------
// Kernel 1: QKV projections as a tensor-core GEMM (f32 acc).
// ---------------------------------------------------------------------------
#define XSTR  272
#define WSTR  144
#define SM_X  0
#define SM_W  17408
#define SM_BI 41472
#define SDSTR 81

__global__ __launch_bounds__(256) void qkv_kernel(
    const float* __restrict__ x,
    const float* __restrict__ Wq, const float* __restrict__ bq,
    const float* __restrict__ Wk, const float* __restrict__ bk,
    const float* __restrict__ Wv, const float* __restrict__ bv)
{
    __shared__ __align__(16) uint8_t sm[41792];
    const uint32_t smb = smem_u32(sm);

    const int t = threadIdx.x, w = t >> 5, l = t & 31;
    const int b = blockIdx.y;
    const int n0 = blockIdx.x * 128;

    float* bs = (float*)(sm + SM_BI);
    if (t < 80) {
        float v;
        if (t < 64)      v = bv[t];
        else if (t < 72) v = bq[t - 64] * L2E;
        else             v = bk[t - 72];
        bs[t] = v;
    }
#pragma unroll
    for (int idx = t; idx < 80 * 32; idx += 256) {
        const int o = idx >> 5, p = idx & 31;
        float lo, hi;
        if (o < 64)      { lo = Wv[o * 64 + 2 * p];          hi = Wv[o * 64 + 2 * p + 1]; }
        else if (o < 72) { lo = Wq[(o - 64) * 64 + 2 * p] * L2E;
                           hi = Wq[(o - 64) * 64 + 2 * p + 1] * L2E; }
        else             { lo = Wk[(o - 72) * 64 + 2 * p];   hi = Wk[(o - 72) * 64 + 2 * p + 1]; }
        *(uint32_t*)(sm + SM_W + o * WSTR + p * 4) = cvt_h2(lo, hi);
    }
    const float* xb = x + (size_t)b * CCH * HW + n0;
#pragma unroll
    for (int idx = t; idx < 64 * 64; idx += 256) {
        const int c = idx >> 6, p = idx & 63;
        float2 v = *(const float2*)(xb + (size_t)c * HW + 2 * p);
        *(uint32_t*)(sm + SM_X + c * XSTR + p * 4) = cvt_h2(v.x, v.y);
    }
    __syncthreads();

    float dacc[10][4];
#pragma unroll
    for (int ct = 0; ct < 10; ct++)
#pragma unroll
        for (int i = 0; i < 4; i++) dacc[ct][i] = 0.0f;

    const int nb = 16 * w;
#pragma unroll
    for (int ks = 0; ks < 4; ks++) {
        uint32_t a[4];
        ldsm4t(a, smb + SM_X
                  + ((l & 7) + ((l >> 4) & 1) * 8 + 16 * ks) * XSTR
                  + (nb + ((l >> 3) & 1) * 8) * 2);
#pragma unroll
        for (int ot = 0; ot < 5; ot++) {
            uint32_t bb[4];
            ldsm4(bb, smb + SM_W + (ot * 16 + ((l >> 4) << 3) + (l & 7)) * WSTR
                      + ks * 32 + ((l >> 3) & 1) * 16);
            mma16(dacc[2 * ot],     a, bb[0], bb[1]);
            mma16(dacc[2 * ot + 1], a, bb[2], bb[3]);
        }
    }

    __syncthreads();
    float* sD = (float*)sm;
    const int r = l >> 2, q = l & 3;
#pragma unroll
    for (int ct = 0; ct < 10; ct++) {
        const int c = ct * 8 + 2 * q;
        sD[(nb + r) * SDSTR + c]         = dacc[ct][0];
        sD[(nb + r) * SDSTR + c + 1]     = dacc[ct][1];
        sD[(nb + r + 8) * SDSTR + c]     = dacc[ct][2];
        sD[(nb + r + 8) * SDSTR + c + 1] = dacc[ct][3];
    }
    __syncthreads();

#pragma unroll
    for (int idx = t; idx < 64 * 64; idx += 256) {
        const int c = idx >> 6, p = idx & 63;
        const float bvv = bs[c];
        const float lo = sD[(2 * p) * SDSTR + c] + bvv;
        const float hi = sD[(2 * p + 1) * SDSTR + c] + bvv;
        *(uint32_t*)(g_Vh + ((size_t)b * CCH + c) * HW + n0 + 2 * p) = cvt_h2(lo, hi);
    }
    {
        const int n = t & 127;
        const int base = (t < 128) ? 64 : 72;
        __half* dst = (t < 128) ? g_Qh : g_Kh;
        uint32_t u[4];
#pragma unroll
        for (int jj = 0; jj < 4; jj++)
            u[jj] = cvt_h2(sD[n * SDSTR + base + 2 * jj] + bs[base + 2 * jj],
                           sD[n * SDSTR + base + 2 * jj + 1] + bs[base + 2 * jj + 1]);
        *(uint4*)(dst + ((size_t)b * HW + n0 + n) * CQD) = make_uint4(u[0], u[1], u[2], u[3]);
    }
}

// ---------------------------------------------------------------------------
// Kernel 2: softmax denominators via f16-acc MMA scores + f16x2 ex2.
// ---------------------------------------------------------------------------
__global__ __launch_bounds__(256) void denom_kernel()
{
    __shared__ __align__(16) uint8_t sm[4096];
    const uint32_t smb = smem_u32(sm);

    const int t = threadIdx.x, w = t >> 5, l = t & 31;
    const int b = blockIdx.z, s = blockIdx.y;
    const int mbase = blockIdx.x * 128;

    const uint4* Qg = (const uint4*)(g_Qh + (size_t)b * HW * CQD);
    const uint4* Kg = (const uint4*)(g_Kh + (size_t)b * HW * CQD);

    if (t < 128) *(uint4*)(sm + t * 16) = Qg[mbase + t];
    __syncthreads();
    uint32_t qa[2];
    ldsm2(qa, smb + (16 * w + (l & 15)) * 16);

    float rs0 = 0.0f, rs1 = 0.0f;
    for (int ch = 0; ch < (HW / NSPL) / 128; ch++) {
        const int nn0 = s * (HW / NSPL) + ch * 128;
        __syncthreads();
        if (t < 128) *(uint4*)(sm + 2048 + t * 16) = Kg[nn0 + t];
        __syncthreads();
        uint32_t kb[16];
        ldsm4(kb + 0,  smb + 2048 + l * 16);
        ldsm4(kb + 4,  smb + 2048 + (32 + l) * 16);
        ldsm4(kb + 8,  smb + 2048 + (64 + l) * 16);
        ldsm4(kb + 12, smb + 2048 + (96 + l) * 16);
        uint32_t a0 = 0u, a1 = 0u;
#pragma unroll
        for (int jj = 0; jj < 16; jj++) {
            uint32_t c0, c1;
            mma8h(c0, c1, qa, kb[jj]);
            a0 = hadd2_(a0, h2ex2(c0));
            a1 = hadd2_(a1, h2ex2(c1));
        }
        float2 f0 = __half22float2(*reinterpret_cast<__half2*>(&a0));
        float2 f1 = __half22float2(*reinterpret_cast<__half2*>(&a1));
        rs0 += f0.x + f0.y;
        rs1 += f1.x + f1.y;
    }
    rs0 += __shfl_xor_sync(0xFFFFFFFFu, rs0, 1);
    rs0 += __shfl_xor_sync(0xFFFFFFFFu, rs0, 2);
    rs1 += __shfl_xor_sync(0xFFFFFFFFu, rs1, 1);
    rs1 += __shfl_xor_sync(0xFFFFFFFFu, rs1, 2);
    if ((l & 3) == 0) {
        const int r = 16 * w + (l >> 2);
        float* dst = g_dpart + ((size_t)s * NBAT + b) * HW + mbase;
        dst[r]     = rs0;
        dst[r + 8] = rs1;
    }
}

// ---------------------------------------------------------------------------
// Kernel 3: prescale V in place (half2): V[c][m] *= 4096/denom[m]
// ---------------------------------------------------------------------------
__global__ __launch_bounds__(256) void vscale_kernel()
{
    const int t = threadIdx.x;
    const int b = blockIdx.y;
    const int m2 = blockIdx.x * 256 + t;
    const int m = 2 * m2;
    float da = g_dpart[(size_t)b * HW + m]
             + g_dpart[((size_t)NBAT + b) * HW + m]
             + g_dpart[((size_t)2 * NBAT + b) * HW + m]
             + g_dpart[((size_t)3 * NBAT + b) * HW + m];
    float db = g_dpart[(size_t)b * HW + m + 1]
             + g_dpart[((size_t)NBAT + b) * HW + m + 1]
             + g_dpart[((size_t)2 * NBAT + b) * HW + m + 1]
             + g_dpart[((size_t)3 * NBAT + b) * HW + m + 1];
    const __half2 inv = __floats2half2_rn(__fdividef(4096.0f, da),
                                          __fdividef(4096.0f, db));
    __half2* Vp = (__half2*)(g_Vh + (size_t)b * CCH * HW) + m2;
#pragma unroll
    for (int c = 0; c < CCH; c++)
        Vp[(size_t)c * (HW / 2)] = __hmul2(Vp[(size_t)c * (HW / 2)], inv);
}

// ---------------------------------------------------------------------------
// Kernel 4: attention aggregation — 4 warps x 32 pixel rows, NS=8 splits
//   for ~5 resident blocks/SM (latency hiding was the R12 bottleneck).
// ---------------------------------------------------------------------------
#define VSTR  272
#define SM_V0 0
#define SM_V1 17408
#define SM_Q0 34816
#define SM_Q1 36864
#define SM_K  38912
#define SMA_BYTES 40960
#define OSTR  65

__global__ __launch_bounds__(128, 5) void attn_kernel()
{
    __shared__ __align__(16) uint8_t sm[SMA_BYTES];
    const uint32_t smb = smem_u32(sm);

    const int t = threadIdx.x, w = t >> 5, l = t & 31;
    const int s = blockIdx.y;
    const int b = blockIdx.z;
    const int n0 = blockIdx.x * 128;

    const uint4* Kg = (const uint4*)(g_Kh + (size_t)b * HW * CQD);
    const uint4* Qg = (const uint4*)(g_Qh + (size_t)b * HW * CQD);
    const uint4* Vg = (const uint4*)(g_Vh + (size_t)b * CCH * HW);

    *(uint4*)(sm + SM_K + t * 16) = Kg[n0 + t];

    auto stage = [&](int buf, int m0) {
        const uint32_t vbase = smb + (buf ? SM_V1 : SM_V0);
#pragma unroll
        for (int jj = 0; jj < 8; jj++) {
            int i = t + jj * 128;
            int row = i >> 4, c16 = i & 15;
            cp16(vbase + row * VSTR + c16 * 16,
                 Vg + (size_t)row * (HW / 8) + (m0 >> 3) + c16);
        }
        cp16(smb + (buf ? SM_Q1 : SM_Q0) + t * 16, Qg + m0 + t);
    };

    stage(0, s * NC * 128);
    CP_COMMIT();

    __syncthreads();
    // warp w owns pixel rows 32w..32w+31: two 16-row A-frag groups
    uint32_t kaA[2], kaB[2];
    ldsm2(kaA, smb + SM_K + (32 * w + (l & 15)) * 16);
    ldsm2(kaB, smb + SM_K + (32 * w + 16 + (l & 15)) * 16);

    uint32_t daccA[8][2], daccB[8][2];
#pragma unroll
    for (int ct = 0; ct < 8; ct++) {
        daccA[ct][0] = daccA[ct][1] = 0u;
        daccB[ct][0] = daccB[ct][1] = 0u;
    }

    for (int chunk = 0; chunk < NC; chunk++) {
        const int buf = chunk & 1;
        if (chunk + 1 < NC) {
            stage(buf ^ 1, (s * NC + chunk + 1) * 128);
            CP_COMMIT();
            CP_WAIT(1);
        } else {
            CP_WAIT(0);
        }
        __syncthreads();

        const uint32_t vbase = smb + (buf ? SM_V1 : SM_V0);
        const uint32_t qbase = smb + (buf ? SM_Q1 : SM_Q0);

        // ---- scores (f16 acc) for both row groups; qb shared ----
        uint32_t paA[8][4], paB[8][4];
#pragma unroll
        for (int half = 0; half < 2; half++) {
            uint32_t qb[8];
            ldsm4(qb + 0, qbase + (64 * half + l) * 16);
            ldsm4(qb + 4, qbase + (64 * half + 32 + l) * 16);
#pragma unroll
            for (int jj = 0; jj < 8; jj++) {
                const int jt = 8 * half + jj;
                uint32_t c0, c1;
                mma8h(c0, c1, kaA, qb[jj]);
                paA[jt >> 1][(jt & 1) * 2]     = h2ex2(c0);
                paA[jt >> 1][(jt & 1) * 2 + 1] = h2ex2(c1);
                mma8h(c0, c1, kaB, qb[jj]);
                paB[jt >> 1][(jt & 1) * 2]     = h2ex2(c0);
                paB[jt >> 1][(jt & 1) * 2 + 1] = h2ex2(c1);
            }
        }

        // ---- D += P @ V'; every V ldsm4 feeds both row groups ----
#pragma unroll
        for (int kk = 0; kk < 8; kk++) {
#pragma unroll
            for (int cp = 0; cp < 4; cp++) {
                uint32_t bb[4];
                ldsm4(bb, vbase
                          + (cp * 16 + ((l >> 4) << 3) + (l & 7)) * VSTR
                          + kk * 32 + ((l >> 3) & 1) * 16);
                mma16h(daccA[2 * cp],     paA[kk], bb[0], bb[1]);
                mma16h(daccA[2 * cp + 1], paA[kk], bb[2], bb[3]);
                mma16h(daccB[2 * cp],     paB[kk], bb[0], bb[1]);
                mma16h(daccB[2 * cp + 1], paB[kk], bb[2], bb[3]);
            }
        }
        __syncthreads();
    }

    // ---- unpack f16 accumulators -> sD -> coalesced [s][b][c][n] writes ----
    float* sD = (float*)sm;
    const int r = l >> 2, q = l & 3;
#pragma unroll
    for (int ct = 0; ct < 8; ct++) {
        const int c = ct * 8 + 2 * q;
        float2 lo = __half22float2(*reinterpret_cast<__half2*>(&daccA[ct][0]));
        float2 hi = __half22float2(*reinterpret_cast<__half2*>(&daccA[ct][1]));
        sD[(32 * w + r) * OSTR + c]          = lo.x;
        sD[(32 * w + r) * OSTR + c + 1]      = lo.y;
        sD[(32 * w + r + 8) * OSTR + c]      = hi.x;
        sD[(32 * w + r + 8) * OSTR + c + 1]  = hi.y;
        lo = __half22float2(*reinterpret_cast<__half2*>(&daccB[ct][0]));
        hi = __half22float2(*reinterpret_cast<__half2*>(&daccB[ct][1]));
        sD[(32 * w + 16 + r) * OSTR + c]         = lo.x;
        sD[(32 * w + 16 + r) * OSTR + c + 1]     = lo.y;
        sD[(32 * w + 24 + r) * OSTR + c]         = hi.x;
        sD[(32 * w + 24 + r) * OSTR + c + 1]     = hi.y;
    }
    __syncthreads();

    float* dst = g_Dp + (size_t)s * PSZ + (size_t)b * CCH * HW;
#pragma unroll
    for (int i = t; i < 128 * CCH; i += 128) {
        const int c = i >> 7, n = i & 127;
        dst[(size_t)c * HW + n0 + n] = sD[n * OSTR + c];
    }
}

// ---------------------------------------------------------------------------
// Kernel 5: combine NS split partials + gamma + residual (vectorized)
// ---------------------------------------------------------------------------
__global__ __launch_bounds__(256) void combine_kernel(
    const float* __restrict__ x,
    const float* __restrict__ gamma,
    float* __restrict__ out)
{
    const size_t i = ((size_t)blockIdx.x * 256 + threadIdx.x) * 4;
    const float gm = gamma[0] * (1.0f / 4096.0f);
    float sx = 0.0f, sy = 0.0f, sz = 0.0f, sw = 0.0f;
#pragma unroll
    for (int s = 0; s < NS; s++) {
        float4 a = *(const float4*)(g_Dp + (size_t)s * PSZ + i);
        sx += a.x; sy += a.y; sz += a.z; sw += a.w;
    }
    float4 xv = *(const float4*)(x + i);
    float4 o;
    o.x = gm * sx + xv.x;
    o.y = gm * sy + xv.y;
    o.z = gm * sz + xv.z;
    o.w = gm * sw + xv.w;
    *(float4*)(out + i) = o;
}

// ---------------------------------------------------------------------------
extern "C" void kernel_launch(void* const* d_in, const int* in_sizes, int n_in,
                              void* d_out, int out_size)
{
    const float* x     = (const float*)d_in[0];
    const float* Wq    = (const float*)d_in[1];
    const float* bq    = (const float*)d_in[2];
    const float* Wk    = (const float*)d_in[3];
    const float* bk    = (const float*)d_in[4];
    const float* Wv    = (const float*)d_in[5];
    const float* bv    = (const float*)d_in[6];
    const float* gamma = (const float*)d_in[7];
    float* out = (float*)d_out;

    qkv_kernel<<<dim3(HW / 128, NBAT), 256>>>(x, Wq, bq, Wk, bk, Wv, bv);
    denom_kernel<<<dim3(HW / 128, NSPL, NBAT), 256>>>();
    vscale_kernel<<<dim3(HW / 512, NBAT), 256>>>();
    attn_kernel<<<dim3(HW / 128, NS, NBAT), 128>>>();
    combine_kernel<<<PSZ / 1024, 256>>>(x, gamma, out);
}

// round 14
// speedup vs baseline: 1.9393x; 1.0042x over previous
#include <cuda_runtime.h>
#include <cuda_fp16.h>
#include <cstdint>

// Problem constants
#define HW   4096
#define CCH  64
#define CQD  8
#define NBAT 4
#define NSPL 4          // denom j-split
#define NS   8          // attn key-split
#define NC   (HW / (NS * 128))   // chunks per attn block = 4
#define PSZ  (NBAT * CCH * HW)
#define L2E  1.4426950408889634f

// Scratch (device globals — no allocation allowed)
__device__ __half g_Qh[NBAT * HW * CQD];      // [b][m][8] fp16, pre-scaled by log2(e)
__device__ __half g_Kh[NBAT * HW * CQD];      // [b][n][8] fp16
__device__ __half g_Vh[NBAT * CCH * HW];      // [b][c][m] fp16 (vscale: *= 4096/denom[m])
__device__ float  g_dpart[NSPL * NBAT * HW];  // per-split softmax denominators
__device__ __half g_Dph[NS * PSZ];            // attn split partials [s][b][c][n], raw f16 accums

// ---------------------------------------------------------------------------
// helpers
// ---------------------------------------------------------------------------
__device__ __forceinline__ uint32_t smem_u32(const void* p) {
    uint32_t a;
    asm("{ .reg .u64 t; cvta.to.shared.u64 t, %1; cvt.u32.u64 %0, t; }" : "=r"(a) : "l"(p));
    return a;
}
__device__ __forceinline__ void ldsm2(uint32_t* r, uint32_t addr) {
    asm volatile("ldmatrix.sync.aligned.m8n8.x2.shared.b16 {%0,%1}, [%2];"
                 : "=r"(r[0]), "=r"(r[1]) : "r"(addr));
}
__device__ __forceinline__ void ldsm4(uint32_t* r, uint32_t addr) {
    asm volatile("ldmatrix.sync.aligned.m8n8.x4.shared.b16 {%0,%1,%2,%3}, [%4];"
                 : "=r"(r[0]), "=r"(r[1]), "=r"(r[2]), "=r"(r[3]) : "r"(addr));
}
__device__ __forceinline__ void ldsm4t(uint32_t* r, uint32_t addr) {
    asm volatile("ldmatrix.sync.aligned.m8n8.x4.trans.shared.b16 {%0,%1,%2,%3}, [%4];"
                 : "=r"(r[0]), "=r"(r[1]), "=r"(r[2]), "=r"(r[3]) : "r"(addr));
}
// scores, f16 accumulate
__device__ __forceinline__ void mma8h(uint32_t& c0, uint32_t& c1,
                                      const uint32_t* a, uint32_t b) {
    asm volatile("mma.sync.aligned.m16n8k8.row.col.f16.f16.f16.f16 "
                 "{%0,%1}, {%2,%3}, {%4}, {%5,%6};"
                 : "=r"(c0), "=r"(c1)
                 : "r"(a[0]), "r"(a[1]), "r"(b), "r"(0u), "r"(0u));
}
// P@V, f16 accumulate
__device__ __forceinline__ void mma16h(uint32_t* d, const uint32_t* a,
                                       uint32_t b0, uint32_t b1) {
    asm volatile("mma.sync.aligned.m16n8k16.row.col.f16.f16.f16.f16 "
                 "{%0,%1}, {%2,%3,%4,%5}, {%6,%7}, {%0,%1};"
                 : "+r"(d[0]), "+r"(d[1])
                 : "r"(a[0]), "r"(a[1]), "r"(a[2]), "r"(a[3]), "r"(b0), "r"(b1));
}
// qkv GEMM keeps f32 accumulate
__device__ __forceinline__ void mma16(float* d, const uint32_t* a,
                                      uint32_t b0, uint32_t b1) {
    asm volatile("mma.sync.aligned.m16n8k16.row.col.f32.f16.f16.f32 "
                 "{%0,%1,%2,%3}, {%4,%5,%6,%7}, {%8,%9}, {%0,%1,%2,%3};"
                 : "+f"(d[0]), "+f"(d[1]), "+f"(d[2]), "+f"(d[3])
                 : "r"(a[0]), "r"(a[1]), "r"(a[2]), "r"(a[3]), "r"(b0), "r"(b1));
}
__device__ __forceinline__ uint32_t cvt_h2(float lo, float hi) {
    uint32_t r;
    asm("cvt.rn.f16x2.f32 %0, %1, %2;" : "=r"(r) : "f"(hi), "f"(lo));
    return r;
}
__device__ __forceinline__ uint32_t h2ex2(uint32_t a) {
    uint32_t r;
    asm("ex2.approx.f16x2 %0, %1;" : "=r"(r) : "r"(a));
    return r;
}
__device__ __forceinline__ uint32_t hadd2_(uint32_t a, uint32_t b) {
    uint32_t r;
    asm("add.f16x2 %0, %1, %2;" : "=r"(r) : "r"(a), "r"(b));
    return r;
}
__device__ __forceinline__ void cp16(uint32_t smem, const void* g) {
    asm volatile("cp.async.cg.shared.global [%0], [%1], 16;" :: "r"(smem), "l"(g));
}
#define CP_COMMIT() asm volatile("cp.async.commit_group;" ::: "memory")
#define CP_WAIT(n)  asm volatile("cp.async.wait_group %0;" :: "n"(n) : "memory")

// ---------------------------------------------------------------------------
// Kernel 1: QKV projections as a tensor-core GEMM (f32 acc).
// ---------------------------------------------------------------------------
#define XSTR  272
#define WSTR  144
#define SM_X  0
#define SM_W  17408
#define SM_BI 41472
#define SDSTR 81

__global__ __launch_bounds__(256) void qkv_kernel(
    const float* __restrict__ x,
    const float* __restrict__ Wq, const float* __restrict__ bq,
    const float* __restrict__ Wk, const float* __restrict__ bk,
    const float* __restrict__ Wv, const float* __restrict__ bv)
{
    __shared__ __align__(16) uint8_t sm[41792];
    const uint32_t smb = smem_u32(sm);

    const int t = threadIdx.x, w = t >> 5, l = t & 31;
    const int b = blockIdx.y;
    const int n0 = blockIdx.x * 128;

    float* bs = (float*)(sm + SM_BI);
    if (t < 80) {
        float v;
        if (t < 64)      v = bv[t];
        else if (t < 72) v = bq[t - 64] * L2E;
        else             v = bk[t - 72];
        bs[t] = v;
    }
#pragma unroll
    for (int idx = t; idx < 80 * 32; idx += 256) {
        const int o = idx >> 5, p = idx & 31;
        float lo, hi;
        if (o < 64)      { lo = Wv[o * 64 + 2 * p];          hi = Wv[o * 64 + 2 * p + 1]; }
        else if (o < 72) { lo = Wq[(o - 64) * 64 + 2 * p] * L2E;
                           hi = Wq[(o - 64) * 64 + 2 * p + 1] * L2E; }
        else             { lo = Wk[(o - 72) * 64 + 2 * p];   hi = Wk[(o - 72) * 64 + 2 * p + 1]; }
        *(uint32_t*)(sm + SM_W + o * WSTR + p * 4) = cvt_h2(lo, hi);
    }
    const float* xb = x + (size_t)b * CCH * HW + n0;
#pragma unroll
    for (int idx = t; idx < 64 * 64; idx += 256) {
        const int c = idx >> 6, p = idx & 63;
        float2 v = *(const float2*)(xb + (size_t)c * HW + 2 * p);
        *(uint32_t*)(sm + SM_X + c * XSTR + p * 4) = cvt_h2(v.x, v.y);
    }
    __syncthreads();

    float dacc[10][4];
#pragma unroll
    for (int ct = 0; ct < 10; ct++)
#pragma unroll
        for (int i = 0; i < 4; i++) dacc[ct][i] = 0.0f;

    const int nb = 16 * w;
#pragma unroll
    for (int ks = 0; ks < 4; ks++) {
        uint32_t a[4];
        ldsm4t(a, smb + SM_X
                  + ((l & 7) + ((l >> 4) & 1) * 8 + 16 * ks) * XSTR
                  + (nb + ((l >> 3) & 1) * 8) * 2);
#pragma unroll
        for (int ot = 0; ot < 5; ot++) {
            uint32_t bb[4];
            ldsm4(bb, smb + SM_W + (ot * 16 + ((l >> 4) << 3) + (l & 7)) * WSTR
                      + ks * 32 + ((l >> 3) & 1) * 16);
            mma16(dacc[2 * ot],     a, bb[0], bb[1]);
            mma16(dacc[2 * ot + 1], a, bb[2], bb[3]);
        }
    }

    __syncthreads();
    float* sD = (float*)sm;
    const int r = l >> 2, q = l & 3;
#pragma unroll
    for (int ct = 0; ct < 10; ct++) {
        const int c = ct * 8 + 2 * q;
        sD[(nb + r) * SDSTR + c]         = dacc[ct][0];
        sD[(nb + r) * SDSTR + c + 1]     = dacc[ct][1];
        sD[(nb + r + 8) * SDSTR + c]     = dacc[ct][2];
        sD[(nb + r + 8) * SDSTR + c + 1] = dacc[ct][3];
    }
    __syncthreads();

#pragma unroll
    for (int idx = t; idx < 64 * 64; idx += 256) {
        const int c = idx >> 6, p = idx & 63;
        const float bvv = bs[c];
        const float lo = sD[(2 * p) * SDSTR + c] + bvv;
        const float hi = sD[(2 * p + 1) * SDSTR + c] + bvv;
        *(uint32_t*)(g_Vh + ((size_t)b * CCH + c) * HW + n0 + 2 * p) = cvt_h2(lo, hi);
    }
    {
        const int n = t & 127;
        const int base = (t < 128) ? 64 : 72;
        __half* dst = (t < 128) ? g_Qh : g_Kh;
        uint32_t u[4];
#pragma unroll
        for (int jj = 0; jj < 4; jj++)
            u[jj] = cvt_h2(sD[n * SDSTR + base + 2 * jj] + bs[base + 2 * jj],
                           sD[n * SDSTR + base + 2 * jj + 1] + bs[base + 2 * jj + 1]);
        *(uint4*)(dst + ((size_t)b * HW + n0 + n) * CQD) = make_uint4(u[0], u[1], u[2], u[3]);
    }
}

// ---------------------------------------------------------------------------
// Kernel 2: softmax denominators — f16-acc MMA scores + f16x2 ex2,
//   K chunks double-buffered via cp.async (one latency-exposed wait less).
// SMEM: Q tile @0 (2048) | K0 @2048 | K1 @4096
// ---------------------------------------------------------------------------
__global__ __launch_bounds__(256) void denom_kernel()
{
    __shared__ __align__(16) uint8_t sm[6144];
    const uint32_t smb = smem_u32(sm);

    const int t = threadIdx.x, w = t >> 5, l = t & 31;
    const int b = blockIdx.z, s = blockIdx.y;
    const int mbase = blockIdx.x * 128;

    const uint4* Qg = (const uint4*)(g_Qh + (size_t)b * HW * CQD);
    const uint4* Kg = (const uint4*)(g_Kh + (size_t)b * HW * CQD);

    if (t < 128) *(uint4*)(sm + t * 16) = Qg[mbase + t];

    auto stageK = [&](int buf, int nn0) {
        if (t < 128) cp16(smb + (buf ? 4096 : 2048) + t * 16, Kg + nn0 + t);
    };
    const int nbase = s * (HW / NSPL);
    stageK(0, nbase);
    CP_COMMIT();

    __syncthreads();
    uint32_t qa[2];
    ldsm2(qa, smb + (16 * w + (l & 15)) * 16);

    float rs0 = 0.0f, rs1 = 0.0f;
    const int NCH = (HW / NSPL) / 128;           // 8
    for (int ch = 0; ch < NCH; ch++) {
        const int buf = ch & 1;
        if (ch + 1 < NCH) {
            stageK(buf ^ 1, nbase + (ch + 1) * 128);
            CP_COMMIT();
            CP_WAIT(1);
        } else {
            CP_WAIT(0);
        }
        __syncthreads();
        const uint32_t kbase = smb + (buf ? 4096 : 2048);
        uint32_t kb[16];
        ldsm4(kb + 0,  kbase + l * 16);
        ldsm4(kb + 4,  kbase + (32 + l) * 16);
        ldsm4(kb + 8,  kbase + (64 + l) * 16);
        ldsm4(kb + 12, kbase + (96 + l) * 16);
        uint32_t a0 = 0u, a1 = 0u;
#pragma unroll
        for (int jj = 0; jj < 16; jj++) {
            uint32_t c0, c1;
            mma8h(c0, c1, qa, kb[jj]);
            a0 = hadd2_(a0, h2ex2(c0));
            a1 = hadd2_(a1, h2ex2(c1));
        }
        float2 f0 = __half22float2(*reinterpret_cast<__half2*>(&a0));
        float2 f1 = __half22float2(*reinterpret_cast<__half2*>(&a1));
        rs0 += f0.x + f0.y;
        rs1 += f1.x + f1.y;
        __syncthreads();
    }
    rs0 += __shfl_xor_sync(0xFFFFFFFFu, rs0, 1);
    rs0 += __shfl_xor_sync(0xFFFFFFFFu, rs0, 2);
    rs1 += __shfl_xor_sync(0xFFFFFFFFu, rs1, 1);
    rs1 += __shfl_xor_sync(0xFFFFFFFFu, rs1, 2);
    if ((l & 3) == 0) {
        const int r = 16 * w + (l >> 2);
        float* dst = g_dpart + ((size_t)s * NBAT + b) * HW + mbase;
        dst[r]     = rs0;
        dst[r + 8] = rs1;
    }
}

// ---------------------------------------------------------------------------
// Kernel 3: prescale V in place (half2): V[c][m] *= 4096/denom[m]
// ---------------------------------------------------------------------------
__global__ __launch_bounds__(256) void vscale_kernel()
{
    const int t = threadIdx.x;
    const int b = blockIdx.y;
    const int m2 = blockIdx.x * 256 + t;
    const int m = 2 * m2;
    float da = g_dpart[(size_t)b * HW + m]
             + g_dpart[((size_t)NBAT + b) * HW + m]
             + g_dpart[((size_t)2 * NBAT + b) * HW + m]
             + g_dpart[((size_t)3 * NBAT + b) * HW + m];
    float db = g_dpart[(size_t)b * HW + m + 1]
             + g_dpart[((size_t)NBAT + b) * HW + m + 1]
             + g_dpart[((size_t)2 * NBAT + b) * HW + m + 1]
             + g_dpart[((size_t)3 * NBAT + b) * HW + m + 1];
    const __half2 inv = __floats2half2_rn(__fdividef(4096.0f, da),
                                          __fdividef(4096.0f, db));
    __half2* Vp = (__half2*)(g_Vh + (size_t)b * CCH * HW) + m2;
#pragma unroll
    for (int c = 0; c < CCH; c++)
        Vp[(size_t)c * (HW / 2)] = __hmul2(Vp[(size_t)c * (HW / 2)], inv);
}

// ---------------------------------------------------------------------------
// Kernel 4: attention aggregation — 4 warps x 32 pixel rows, NS=8 splits.
//   Split partials now stored as raw f16 accumulator values (identical math,
//   half the global traffic).
// ---------------------------------------------------------------------------
#define VSTR  272
#define SM_V0 0
#define SM_V1 17408
#define SM_Q0 34816
#define SM_Q1 36864
#define SM_K  38912
#define SMA_BYTES 40960
#define OSTR  65

__global__ __launch_bounds__(128, 5) void attn_kernel()
{
    __shared__ __align__(16) uint8_t sm[SMA_BYTES];
    const uint32_t smb = smem_u32(sm);

    const int t = threadIdx.x, w = t >> 5, l = t & 31;
    const int s = blockIdx.y;
    const int b = blockIdx.z;
    const int n0 = blockIdx.x * 128;

    const uint4* Kg = (const uint4*)(g_Kh + (size_t)b * HW * CQD);
    const uint4* Qg = (const uint4*)(g_Qh + (size_t)b * HW * CQD);
    const uint4* Vg = (const uint4*)(g_Vh + (size_t)b * CCH * HW);

    *(uint4*)(sm + SM_K + t * 16) = Kg[n0 + t];

    auto stage = [&](int buf, int m0) {
        const uint32_t vbase = smb + (buf ? SM_V1 : SM_V0);
#pragma unroll
        for (int jj = 0; jj < 8; jj++) {
            int i = t + jj * 128;
            int row = i >> 4, c16 = i & 15;
            cp16(vbase + row * VSTR + c16 * 16,
                 Vg + (size_t)row * (HW / 8) + (m0 >> 3) + c16);
        }
        cp16(smb + (buf ? SM_Q1 : SM_Q0) + t * 16, Qg + m0 + t);
    };

    stage(0, s * NC * 128);
    CP_COMMIT();

    __syncthreads();
    // warp w owns pixel rows 32w..32w+31: two 16-row A-frag groups
    uint32_t kaA[2], kaB[2];
    ldsm2(kaA, smb + SM_K + (32 * w + (l & 15)) * 16);
    ldsm2(kaB, smb + SM_K + (32 * w + 16 + (l & 15)) * 16);

    uint32_t daccA[8][2], daccB[8][2];
#pragma unroll
    for (int ct = 0; ct < 8; ct++) {
        daccA[ct][0] = daccA[ct][1] = 0u;
        daccB[ct][0] = daccB[ct][1] = 0u;
    }

    for (int chunk = 0; chunk < NC; chunk++) {
        const int buf = chunk & 1;
        if (chunk + 1 < NC) {
            stage(buf ^ 1, (s * NC + chunk + 1) * 128);
            CP_COMMIT();
            CP_WAIT(1);
        } else {
            CP_WAIT(0);
        }
        __syncthreads();

        const uint32_t vbase = smb + (buf ? SM_V1 : SM_V0);
        const uint32_t qbase = smb + (buf ? SM_Q1 : SM_Q0);

        // ---- scores (f16 acc) for both row groups; qb shared ----
        uint32_t paA[8][4], paB[8][4];
#pragma unroll
        for (int half = 0; half < 2; half++) {
            uint32_t qb[8];
            ldsm4(qb + 0, qbase + (64 * half + l) * 16);
            ldsm4(qb + 4, qbase + (64 * half + 32 + l) * 16);
#pragma unroll
            for (int jj = 0; jj < 8; jj++) {
                const int jt = 8 * half + jj;
                uint32_t c0, c1;
                mma8h(c0, c1, kaA, qb[jj]);
                paA[jt >> 1][(jt & 1) * 2]     = h2ex2(c0);
                paA[jt >> 1][(jt & 1) * 2 + 1] = h2ex2(c1);
                mma8h(c0, c1, kaB, qb[jj]);
                paB[jt >> 1][(jt & 1) * 2]     = h2ex2(c0);
                paB[jt >> 1][(jt & 1) * 2 + 1] = h2ex2(c1);
            }
        }

        // ---- D += P @ V'; every V ldsm4 feeds both row groups ----
#pragma unroll
        for (int kk = 0; kk < 8; kk++) {
#pragma unroll
            for (int cp = 0; cp < 4; cp++) {
                uint32_t bb[4];
                ldsm4(bb, vbase
                          + (cp * 16 + ((l >> 4) << 3) + (l & 7)) * VSTR
                          + kk * 32 + ((l >> 3) & 1) * 16);
                mma16h(daccA[2 * cp],     paA[kk], bb[0], bb[1]);
                mma16h(daccA[2 * cp + 1], paA[kk], bb[2], bb[3]);
                mma16h(daccB[2 * cp],     paB[kk], bb[0], bb[1]);
                mma16h(daccB[2 * cp + 1], paB[kk], bb[2], bb[3]);
            }
        }
        __syncthreads();
    }

    // ---- f16 accs -> f32 smem stage (for transpose) -> f16 global writes ----
    float* sD = (float*)sm;
    const int r = l >> 2, q = l & 3;
#pragma unroll
    for (int ct = 0; ct < 8; ct++) {
        const int c = ct * 8 + 2 * q;
        float2 lo = __half22float2(*reinterpret_cast<__half2*>(&daccA[ct][0]));
        float2 hi = __half22float2(*reinterpret_cast<__half2*>(&daccA[ct][1]));
        sD[(32 * w + r) * OSTR + c]          = lo.x;
        sD[(32 * w + r) * OSTR + c + 1]      = lo.y;
        sD[(32 * w + r + 8) * OSTR + c]      = hi.x;
        sD[(32 * w + r + 8) * OSTR + c + 1]  = hi.y;
        lo = __half22float2(*reinterpret_cast<__half2*>(&daccB[ct][0]));
        hi = __half22float2(*reinterpret_cast<__half2*>(&daccB[ct][1]));
        sD[(32 * w + 16 + r) * OSTR + c]         = lo.x;
        sD[(32 * w + 16 + r) * OSTR + c + 1]     = lo.y;
        sD[(32 * w + 24 + r) * OSTR + c]         = hi.x;
        sD[(32 * w + 24 + r) * OSTR + c + 1]     = hi.y;
    }
    __syncthreads();

    __half* dst = g_Dph + (size_t)s * PSZ + (size_t)b * CCH * HW;
#pragma unroll
    for (int i = t; i < 64 * 64; i += 128) {
        const int c = i >> 6, p = i & 63;          // p = pixel pair
        const float lo = sD[(2 * p) * OSTR + c];
        const float hi = sD[(2 * p + 1) * OSTR + c];
        *(uint32_t*)(dst + (size_t)c * HW + n0 + 2 * p) = cvt_h2(lo, hi);
    }
}

// ---------------------------------------------------------------------------
// Kernel 5: combine NS f16 split partials + gamma + residual.
//   8 pixels per thread via uint4-of-halves loads.
// ---------------------------------------------------------------------------
__global__ __launch_bounds__(256) void combine_kernel(
    const float* __restrict__ x,
    const float* __restrict__ gamma,
    float* __restrict__ out)
{
    const size_t i = ((size_t)blockIdx.x * 256 + threadIdx.x) * 8;
    const float gm = gamma[0] * (1.0f / 4096.0f);
    float acc[8];
#pragma unroll
    for (int k = 0; k < 8; k++) acc[k] = 0.0f;
#pragma unroll
    for (int s = 0; s < NS; s++) {
        uint4 v = *(const uint4*)(g_Dph + (size_t)s * PSZ + i);
        float2 f;
        f = __half22float2(*reinterpret_cast<__half2*>(&v.x)); acc[0] += f.x; acc[1] += f.y;
        f = __half22float2(*reinterpret_cast<__half2*>(&v.y)); acc[2] += f.x; acc[3] += f.y;
        f = __half22float2(*reinterpret_cast<__half2*>(&v.z)); acc[4] += f.x; acc[5] += f.y;
        f = __half22float2(*reinterpret_cast<__half2*>(&v.w)); acc[6] += f.x; acc[7] += f.y;
    }
    float4 x0 = *(const float4*)(x + i);
    float4 x1 = *(const float4*)(x + i + 4);
    float4 o0, o1;
    o0.x = gm * acc[0] + x0.x;  o0.y = gm * acc[1] + x0.y;
    o0.z = gm * acc[2] + x0.z;  o0.w = gm * acc[3] + x0.w;
    o1.x = gm * acc[4] + x1.x;  o1.y = gm * acc[5] + x1.y;
    o1.z = gm * acc[6] + x1.z;  o1.w = gm * acc[7] + x1.w;
    *(float4*)(out + i)     = o0;
    *(float4*)(out + i + 4) = o1;
}

// ---------------------------------------------------------------------------
extern "C" void kernel_launch(void* const* d_in, const int* in_sizes, int n_in,
                              void* d_out, int out_size)
{
    const float* x     = (const float*)d_in[0];
    const float* Wq    = (const float*)d_in[1];
    const float* bq    = (const float*)d_in[2];
    const float* Wk    = (const float*)d_in[3];
    const float* bk    = (const float*)d_in[4];
    const float* Wv    = (const float*)d_in[5];
    const float* bv    = (const float*)d_in[6];
    const float* gamma = (const float*)d_in[7];
    float* out = (float*)d_out;

    qkv_kernel<<<dim3(HW / 128, NBAT), 256>>>(x, Wq, bq, Wk, bk, Wv, bv);
    denom_kernel<<<dim3(HW / 128, NSPL, NBAT), 256>>>();
    vscale_kernel<<<dim3(HW / 512, NBAT), 256>>>();
    attn_kernel<<<dim3(HW / 128, NS, NBAT), 128>>>();
    combine_kernel<<<PSZ / 2048, 256>>>(x, gamma, out);
}

// round 16
// speedup vs baseline: 2.0161x; 1.0396x over previous
#include <cuda_runtime.h>
#include <cuda_fp16.h>
#include <cstdint>

// Problem constants
#define HW   4096
#define CCH  64
#define CQD  8
#define NBAT 4
#define NSPL 4          // denom j-split
#define NS   8          // attn key-split
#define NC   (HW / (NS * 128))   // chunks per attn block = 4
#define PSZ  (NBAT * CCH * HW)
#define L2E  1.4426950408889634f

// Scratch (device globals — no allocation allowed)
__device__ __half g_Qh[NBAT * HW * CQD];      // [b][m][8] fp16, pre-scaled by log2(e)
__device__ __half g_Kh[NBAT * HW * CQD];      // [b][n][8] fp16
__device__ __half g_Vh[NBAT * CCH * HW];      // [b][c][m] fp16 (raw; normalization via bias)
__device__ float  g_dpart[NSPL * NBAT * HW];  // per-split softmax denominators
__device__ __half g_bias[NBAT * HW];          // 12 - log2(denom[m]), f16
__device__ __half g_Dph[NS * PSZ];            // attn split partials [s][b][c][n], raw f16 accums

// ---------------------------------------------------------------------------
// helpers
// ---------------------------------------------------------------------------
__device__ __forceinline__ uint32_t smem_u32(const void* p) {
    uint32_t a;
    asm("{ .reg .u64 t; cvta.to.shared.u64 t, %1; cvt.u32.u64 %0, t; }" : "=r"(a) : "l"(p));
    return a;
}
__device__ __forceinline__ void ldsm2(uint32_t* r, uint32_t addr) {
    asm volatile("ldmatrix.sync.aligned.m8n8.x2.shared.b16 {%0,%1}, [%2];"
                 : "=r"(r[0]), "=r"(r[1]) : "r"(addr));
}
__device__ __forceinline__ void ldsm4(uint32_t* r, uint32_t addr) {
    asm volatile("ldmatrix.sync.aligned.m8n8.x4.shared.b16 {%0,%1,%2,%3}, [%4];"
                 : "=r"(r[0]), "=r"(r[1]), "=r"(r[2]), "=r"(r[3]) : "r"(addr));
}
__device__ __forceinline__ void ldsm4t(uint32_t* r, uint32_t addr) {
    asm volatile("ldmatrix.sync.aligned.m8n8.x4.trans.shared.b16 {%0,%1,%2,%3}, [%4];"
                 : "=r"(r[0]), "=r"(r[1]), "=r"(r[2]), "=r"(r[3]) : "r"(addr));
}
// scores, f16 accumulate, zero C init (denom)
__device__ __forceinline__ void mma8h(uint32_t& c0, uint32_t& c1,
                                      const uint32_t* a, uint32_t b) {
    asm volatile("mma.sync.aligned.m16n8k8.row.col.f16.f16.f16.f16 "
                 "{%0,%1}, {%2,%3}, {%4}, {%5,%6};"
                 : "=r"(c0), "=r"(c1)
                 : "r"(a[0]), "r"(a[1]), "r"(b), "r"(0u), "r"(0u));
}
// scores with per-column bias C init (attn: softmax normalization folded in)
__device__ __forceinline__ void mma8hb(uint32_t& c0, uint32_t& c1,
                                       const uint32_t* a, uint32_t b, uint32_t bias) {
    asm volatile("mma.sync.aligned.m16n8k8.row.col.f16.f16.f16.f16 "
                 "{%0,%1}, {%2,%3}, {%4}, {%5,%6};"
                 : "=r"(c0), "=r"(c1)
                 : "r"(a[0]), "r"(a[1]), "r"(b), "r"(bias), "r"(bias));
}
// P@V, f16 accumulate
__device__ __forceinline__ void mma16h(uint32_t* d, const uint32_t* a,
                                       uint32_t b0, uint32_t b1) {
    asm volatile("mma.sync.aligned.m16n8k16.row.col.f16.f16.f16.f16 "
                 "{%0,%1}, {%2,%3,%4,%5}, {%6,%7}, {%0,%1};"
                 : "+r"(d[0]), "+r"(d[1])
                 : "r"(a[0]), "r"(a[1]), "r"(a[2]), "r"(a[3]), "r"(b0), "r"(b1));
}
// qkv GEMM keeps f32 accumulate
__device__ __forceinline__ void mma16(float* d, const uint32_t* a,
                                      uint32_t b0, uint32_t b1) {
    asm volatile("mma.sync.aligned.m16n8k16.row.col.f32.f16.f16.f32 "
                 "{%0,%1,%2,%3}, {%4,%5,%6,%7}, {%8,%9}, {%0,%1,%2,%3};"
                 : "+f"(d[0]), "+f"(d[1]), "+f"(d[2]), "+f"(d[3])
                 : "r"(a[0]), "r"(a[1]), "r"(a[2]), "r"(a[3]), "r"(b0), "r"(b1));
}
__device__ __forceinline__ uint32_t cvt_h2(float lo, float hi) {
    uint32_t r;
    asm("cvt.rn.f16x2.f32 %0, %1, %2;" : "=r"(r) : "f"(hi), "f"(lo));
    return r;
}
__device__ __forceinline__ uint32_t h2ex2(uint32_t a) {
    uint32_t r;
    asm("ex2.approx.f16x2 %0, %1;" : "=r"(r) : "r"(a));
    return r;
}
__device__ __forceinline__ uint32_t hadd2_(uint32_t a, uint32_t b) {
    uint32_t r;
    asm("add.f16x2 %0, %1, %2;" : "=r"(r) : "r"(a), "r"(b));
    return r;
}
__device__ __forceinline__ void cp16(uint32_t smem, const void* g) {
    asm volatile("cp.async.cg.shared.global [%0], [%1], 16;" :: "r"(smem), "l"(g));
}
#define CP_COMMIT() asm volatile("cp.async.commit_group;" ::: "memory")
#define CP_WAIT(n)  asm volatile("cp.async.wait_group %0;" :: "n"(n) : "memory")

// ---------------------------------------------------------------------------
// Kernel 1: QKV projections as a tensor-core GEMM (f32 acc).
// ---------------------------------------------------------------------------
#define XSTR  272
#define WSTR  144
#define SM_X  0
#define SM_W  17408
#define SM_BI 41472
#define SDSTR 81

__global__ __launch_bounds__(256) void qkv_kernel(
    const float* __restrict__ x,
    const float* __restrict__ Wq, const float* __restrict__ bq,
    const float* __restrict__ Wk, const float* __restrict__ bk,
    const float* __restrict__ Wv, const float* __restrict__ bv)
{
    __shared__ __align__(16) uint8_t sm[41792];
    const uint32_t smb = smem_u32(sm);

    const int t = threadIdx.x, w = t >> 5, l = t & 31;
    const int b = blockIdx.y;
    const int n0 = blockIdx.x * 128;

    float* bs = (float*)(sm + SM_BI);
    if (t < 80) {
        float v;
        if (t < 64)      v = bv[t];
        else if (t < 72) v = bq[t - 64] * L2E;
        else             v = bk[t - 72];
        bs[t] = v;
    }
#pragma unroll
    for (int idx = t; idx < 80 * 32; idx += 256) {
        const int o = idx >> 5, p = idx & 31;
        float lo, hi;
        if (o < 64)      { lo = Wv[o * 64 + 2 * p];          hi = Wv[o * 64 + 2 * p + 1]; }
        else if (o < 72) { lo = Wq[(o - 64) * 64 + 2 * p] * L2E;
                           hi = Wq[(o - 64) * 64 + 2 * p + 1] * L2E; }
        else             { lo = Wk[(o - 72) * 64 + 2 * p];   hi = Wk[(o - 72) * 64 + 2 * p + 1]; }
        *(uint32_t*)(sm + SM_W + o * WSTR + p * 4) = cvt_h2(lo, hi);
    }
    const float* xb = x + (size_t)b * CCH * HW + n0;
#pragma unroll
    for (int idx = t; idx < 64 * 64; idx += 256) {
        const int c = idx >> 6, p = idx & 63;
        float2 v = *(const float2*)(xb + (size_t)c * HW + 2 * p);
        *(uint32_t*)(sm + SM_X + c * XSTR + p * 4) = cvt_h2(v.x, v.y);
    }
    __syncthreads();

    float dacc[10][4];
#pragma unroll
    for (int ct = 0; ct < 10; ct++)
#pragma unroll
        for (int i = 0; i < 4; i++) dacc[ct][i] = 0.0f;

    const int nb = 16 * w;
#pragma unroll
    for (int ks = 0; ks < 4; ks++) {
        uint32_t a[4];
        ldsm4t(a, smb + SM_X
                  + ((l & 7) + ((l >> 4) & 1) * 8 + 16 * ks) * XSTR
                  + (nb + ((l >> 3) & 1) * 8) * 2);
#pragma unroll
        for (int ot = 0; ot < 5; ot++) {
            uint32_t bb[4];
            ldsm4(bb, smb + SM_W + (ot * 16 + ((l >> 4) << 3) + (l & 7)) * WSTR
                      + ks * 32 + ((l >> 3) & 1) * 16);
            mma16(dacc[2 * ot],     a, bb[0], bb[1]);
            mma16(dacc[2 * ot + 1], a, bb[2], bb[3]);
        }
    }

    __syncthreads();
    float* sD = (float*)sm;
    const int r = l >> 2, q = l & 3;
#pragma unroll
    for (int ct = 0; ct < 10; ct++) {
        const int c = ct * 8 + 2 * q;
        sD[(nb + r) * SDSTR + c]         = dacc[ct][0];
        sD[(nb + r) * SDSTR + c + 1]     = dacc[ct][1];
        sD[(nb + r + 8) * SDSTR + c]     = dacc[ct][2];
        sD[(nb + r + 8) * SDSTR + c + 1] = dacc[ct][3];
    }
    __syncthreads();

#pragma unroll
    for (int idx = t; idx < 64 * 64; idx += 256) {
        const int c = idx >> 6, p = idx & 63;
        const float bvv = bs[c];
        const float lo = sD[(2 * p) * SDSTR + c] + bvv;
        const float hi = sD[(2 * p + 1) * SDSTR + c] + bvv;
        *(uint32_t*)(g_Vh + ((size_t)b * CCH + c) * HW + n0 + 2 * p) = cvt_h2(lo, hi);
    }
    {
        const int n = t & 127;
        const int base = (t < 128) ? 64 : 72;
        __half* dst = (t < 128) ? g_Qh : g_Kh;
        uint32_t u[4];
#pragma unroll
        for (int jj = 0; jj < 4; jj++)
            u[jj] = cvt_h2(sD[n * SDSTR + base + 2 * jj] + bs[base + 2 * jj],
                           sD[n * SDSTR + base + 2 * jj + 1] + bs[base + 2 * jj + 1]);
        *(uint4*)(dst + ((size_t)b * HW + n0 + n) * CQD) = make_uint4(u[0], u[1], u[2], u[3]);
    }
}

// ---------------------------------------------------------------------------
// Kernel 2: softmax denominators — f16-acc MMA scores + f16x2 ex2,
//   K chunks double-buffered via cp.async.
// ---------------------------------------------------------------------------
__global__ __launch_bounds__(256) void denom_kernel()
{
    __shared__ __align__(16) uint8_t sm[6144];
    const uint32_t smb = smem_u32(sm);

    const int t = threadIdx.x, w = t >> 5, l = t & 31;
    const int b = blockIdx.z, s = blockIdx.y;
    const int mbase = blockIdx.x * 128;

    const uint4* Qg = (const uint4*)(g_Qh + (size_t)b * HW * CQD);
    const uint4* Kg = (const uint4*)(g_Kh + (size_t)b * HW * CQD);

    if (t < 128) *(uint4*)(sm + t * 16) = Qg[mbase + t];

    auto stageK = [&](int buf, int nn0) {
        if (t < 128) cp16(smb + (buf ? 4096 : 2048) + t * 16, Kg + nn0 + t);
    };
    const int nbase = s * (HW / NSPL);
    stageK(0, nbase);
    CP_COMMIT();

    __syncthreads();
    uint32_t qa[2];
    ldsm2(qa, smb + (16 * w + (l & 15)) * 16);

    float rs0 = 0.0f, rs1 = 0.0f;
    const int NCH = (HW / NSPL) / 128;           // 8
    for (int ch = 0; ch < NCH; ch++) {
        const int buf = ch & 1;
        if (ch + 1 < NCH) {
            stageK(buf ^ 1, nbase + (ch + 1) * 128);
            CP_COMMIT();
            CP_WAIT(1);
        } else {
            CP_WAIT(0);
        }
        __syncthreads();
        const uint32_t kbase = smb + (buf ? 4096 : 2048);
        uint32_t kb[16];
        ldsm4(kb + 0,  kbase + l * 16);
        ldsm4(kb + 4,  kbase + (32 + l) * 16);
        ldsm4(kb + 8,  kbase + (64 + l) * 16);
        ldsm4(kb + 12, kbase + (96 + l) * 16);
        uint32_t a0 = 0u, a1 = 0u;
#pragma unroll
        for (int jj = 0; jj < 16; jj++) {
            uint32_t c0, c1;
            mma8h(c0, c1, qa, kb[jj]);
            a0 = hadd2_(a0, h2ex2(c0));
            a1 = hadd2_(a1, h2ex2(c1));
        }
        float2 f0 = __half22float2(*reinterpret_cast<__half2*>(&a0));
        float2 f1 = __half22float2(*reinterpret_cast<__half2*>(&a1));
        rs0 += f0.x + f0.y;
        rs1 += f1.x + f1.y;
        __syncthreads();
    }
    rs0 += __shfl_xor_sync(0xFFFFFFFFu, rs0, 1);
    rs0 += __shfl_xor_sync(0xFFFFFFFFu, rs0, 2);
    rs1 += __shfl_xor_sync(0xFFFFFFFFu, rs1, 1);
    rs1 += __shfl_xor_sync(0xFFFFFFFFu, rs1, 2);
    if ((l & 3) == 0) {
        const int r = 16 * w + (l >> 2);
        float* dst = g_dpart + ((size_t)s * NBAT + b) * HW + mbase;
        dst[r]     = rs0;
        dst[r + 8] = rs1;
    }
}

// ---------------------------------------------------------------------------
// Kernel 3: finalize — bias[m] = 12 - log2(denom[m])  (f16)
// ---------------------------------------------------------------------------
__global__ __launch_bounds__(256) void finalize_kernel()
{
    const int i = blockIdx.x * 256 + threadIdx.x;   // over NBAT*HW
    float d = g_dpart[i]
            + g_dpart[(size_t)NBAT * HW + i]
            + g_dpart[(size_t)2 * NBAT * HW + i]
            + g_dpart[(size_t)3 * NBAT * HW + i];
    g_bias[i] = __float2half(12.0f - __log2f(d));
}

// ---------------------------------------------------------------------------
// Kernel 4: attention aggregation — 4 warps x 32 pixel rows, NS=8 splits.
//   Softmax normalization folded into score MMA C-init (per-key bias).
// SMEM: V0 @0 | V1 @17408 | Q0 @34816 | Q1 @36864 | K @38912
//       | bias0 @40960 | bias1 @41216
// ---------------------------------------------------------------------------
#define VSTR  272
#define SM_V0 0
#define SM_V1 17408
#define SM_Q0 34816
#define SM_Q1 36864
#define SM_K  38912
#define SM_B0 40960
#define SM_B1 41216
#define SMA_BYTES 41472
#define OSTR  65

__global__ __launch_bounds__(128, 5) void attn_kernel()
{
    __shared__ __align__(16) uint8_t sm[SMA_BYTES];
    const uint32_t smb = smem_u32(sm);

    const int t = threadIdx.x, w = t >> 5, l = t & 31;
    const int s = blockIdx.y;
    const int b = blockIdx.z;
    const int n0 = blockIdx.x * 128;

    const uint4* Kg = (const uint4*)(g_Kh + (size_t)b * HW * CQD);
    const uint4* Qg = (const uint4*)(g_Qh + (size_t)b * HW * CQD);
    const uint4* Vg = (const uint4*)(g_Vh + (size_t)b * CCH * HW);
    const __half* Bg = g_bias + (size_t)b * HW;

    *(uint4*)(sm + SM_K + t * 16) = Kg[n0 + t];

    auto stage = [&](int buf, int m0) {
        const uint32_t vbase = smb + (buf ? SM_V1 : SM_V0);
#pragma unroll
        for (int jj = 0; jj < 8; jj++) {
            int i = t + jj * 128;
            int row = i >> 4, c16 = i & 15;
            cp16(vbase + row * VSTR + c16 * 16,
                 Vg + (size_t)row * (HW / 8) + (m0 >> 3) + c16);
        }
        cp16(smb + (buf ? SM_Q1 : SM_Q0) + t * 16, Qg + m0 + t);
        if (t < 16) cp16(smb + (buf ? SM_B1 : SM_B0) + t * 16, Bg + m0 + t * 8);
    };

    stage(0, s * NC * 128);
    CP_COMMIT();

    __syncthreads();
    // warp w owns pixel rows 32w..32w+31: two 16-row A-frag groups
    uint32_t kaA[2], kaB[2];
    ldsm2(kaA, smb + SM_K + (32 * w + (l & 15)) * 16);
    ldsm2(kaB, smb + SM_K + (32 * w + 16 + (l & 15)) * 16);

    uint32_t daccA[8][2], daccB[8][2];
#pragma unroll
    for (int ct = 0; ct < 8; ct++) {
        daccA[ct][0] = daccA[ct][1] = 0u;
        daccB[ct][0] = daccB[ct][1] = 0u;
    }

    for (int chunk = 0; chunk < NC; chunk++) {
        const int buf = chunk & 1;
        if (chunk + 1 < NC) {
            stage(buf ^ 1, (s * NC + chunk + 1) * 128);
            CP_COMMIT();
            CP_WAIT(1);
        } else {
            CP_WAIT(0);
        }
        __syncthreads();

        const uint32_t vbase = smb + (buf ? SM_V1 : SM_V0);
        const uint32_t qbase = smb + (buf ? SM_Q1 : SM_Q0);
        // generic-pointer view for scalar bias reads (LDS via C dereference)
        const uint8_t* bptr = sm + (buf ? SM_B1 : SM_B0);

        // ---- scores with bias C-init (normalization free) ----
        uint32_t paA[8][4], paB[8][4];
#pragma unroll
        for (int half = 0; half < 2; half++) {
            uint32_t qb[8];
            ldsm4(qb + 0, qbase + (64 * half + l) * 16);
            ldsm4(qb + 4, qbase + (64 * half + 32 + l) * 16);
#pragma unroll
            for (int jj = 0; jj < 8; jj++) {
                const int jt = 8 * half + jj;
                const uint32_t bias = *(const uint32_t*)(bptr + (jt * 4 + (l & 3)) * 4);
                uint32_t c0, c1;
                mma8hb(c0, c1, kaA, qb[jj], bias);
                paA[jt >> 1][(jt & 1) * 2]     = h2ex2(c0);
                paA[jt >> 1][(jt & 1) * 2 + 1] = h2ex2(c1);
                mma8hb(c0, c1, kaB, qb[jj], bias);
                paB[jt >> 1][(jt & 1) * 2]     = h2ex2(c0);
                paB[jt >> 1][(jt & 1) * 2 + 1] = h2ex2(c1);
            }
        }

        // ---- D += P @ V; every V ldsm4 feeds both row groups ----
#pragma unroll
        for (int kk = 0; kk < 8; kk++) {
#pragma unroll
            for (int cp = 0; cp < 4; cp++) {
                uint32_t bb[4];
                ldsm4(bb, vbase
                          + (cp * 16 + ((l >> 4) << 3) + (l & 7)) * VSTR
                          + kk * 32 + ((l >> 3) & 1) * 16);
                mma16h(daccA[2 * cp],     paA[kk], bb[0], bb[1]);
                mma16h(daccA[2 * cp + 1], paA[kk], bb[2], bb[3]);
                mma16h(daccB[2 * cp],     paB[kk], bb[0], bb[1]);
                mma16h(daccB[2 * cp + 1], paB[kk], bb[2], bb[3]);
            }
        }
        __syncthreads();
    }

    // ---- f16 accs -> f32 smem stage (transpose) -> f16 global writes ----
    float* sD = (float*)sm;
    const int r = l >> 2, q = l & 3;
#pragma unroll
    for (int ct = 0; ct < 8; ct++) {
        const int c = ct * 8 + 2 * q;
        float2 lo = __half22float2(*reinterpret_cast<__half2*>(&daccA[ct][0]));
        float2 hi = __half22float2(*reinterpret_cast<__half2*>(&daccA[ct][1]));
        sD[(32 * w + r) * OSTR + c]          = lo.x;
        sD[(32 * w + r) * OSTR + c + 1]      = lo.y;
        sD[(32 * w + r + 8) * OSTR + c]      = hi.x;
        sD[(32 * w + r + 8) * OSTR + c + 1]  = hi.y;
        lo = __half22float2(*reinterpret_cast<__half2*>(&daccB[ct][0]));
        hi = __half22float2(*reinterpret_cast<__half2*>(&daccB[ct][1]));
        sD[(32 * w + 16 + r) * OSTR + c]         = lo.x;
        sD[(32 * w + 16 + r) * OSTR + c + 1]     = lo.y;
        sD[(32 * w + 24 + r) * OSTR + c]         = hi.x;
        sD[(32 * w + 24 + r) * OSTR + c + 1]     = hi.y;
    }
    __syncthreads();

    __half* dst = g_Dph + (size_t)s * PSZ + (size_t)b * CCH * HW;
#pragma unroll
    for (int i = t; i < 64 * 64; i += 128) {
        const int c = i >> 6, p = i & 63;          // p = pixel pair
        const float lo = sD[(2 * p) * OSTR + c];
        const float hi = sD[(2 * p + 1) * OSTR + c];
        *(uint32_t*)(dst + (size_t)c * HW + n0 + 2 * p) = cvt_h2(lo, hi);
    }
}

// ---------------------------------------------------------------------------
// Kernel 5: combine NS f16 split partials + gamma + residual.
// ---------------------------------------------------------------------------
__global__ __launch_bounds__(256) void combine_kernel(
    const float* __restrict__ x,
    const float* __restrict__ gamma,
    float* __restrict__ out)
{
    const size_t i = ((size_t)blockIdx.x * 256 + threadIdx.x) * 8;
    const float gm = gamma[0] * (1.0f / 4096.0f);
    float acc[8];
#pragma unroll
    for (int k = 0; k < 8; k++) acc[k] = 0.0f;
#pragma unroll
    for (int s = 0; s < NS; s++) {
        uint4 v = *(const uint4*)(g_Dph + (size_t)s * PSZ + i);
        float2 f;
        f = __half22float2(*reinterpret_cast<__half2*>(&v.x)); acc[0] += f.x; acc[1] += f.y;
        f = __half22float2(*reinterpret_cast<__half2*>(&v.y)); acc[2] += f.x; acc[3] += f.y;
        f = __half22float2(*reinterpret_cast<__half2*>(&v.z)); acc[4] += f.x; acc[5] += f.y;
        f = __half22float2(*reinterpret_cast<__half2*>(&v.w)); acc[6] += f.x; acc[7] += f.y;
    }
    float4 x0 = *(const float4*)(x + i);
    float4 x1 = *(const float4*)(x + i + 4);
    float4 o0, o1;
    o0.x = gm * acc[0] + x0.x;  o0.y = gm * acc[1] + x0.y;
    o0.z = gm * acc[2] + x0.z;  o0.w = gm * acc[3] + x0.w;
    o1.x = gm * acc[4] + x1.x;  o1.y = gm * acc[5] + x1.y;
    o1.z = gm * acc[6] + x1.z;  o1.w = gm * acc[7] + x1.w;
    *(float4*)(out + i)     = o0;
    *(float4*)(out + i + 4) = o1;
}

// ---------------------------------------------------------------------------
extern "C" void kernel_launch(void* const* d_in, const int* in_sizes, int n_in,
                              void* d_out, int out_size)
{
    const float* x     = (const float*)d_in[0];
    const float* Wq    = (const float*)d_in[1];
    const float* bq    = (const float*)d_in[2];
    const float* Wk    = (const float*)d_in[3];
    const float* bk    = (const float*)d_in[4];
    const float* Wv    = (const float*)d_in[5];
    const float* bv    = (const float*)d_in[6];
    const float* gamma = (const float*)d_in[7];
    float* out = (float*)d_out;

    qkv_kernel<<<dim3(HW / 128, NBAT), 256>>>(x, Wq, bq, Wk, bk, Wv, bv);
    denom_kernel<<<dim3(HW / 128, NSPL, NBAT), 256>>>();
    finalize_kernel<<<(NBAT * HW) / 256, 256>>>();
    attn_kernel<<<dim3(HW / 128, NS, NBAT), 128>>>();
    combine_kernel<<<PSZ / 2048, 256>>>(x, gamma, out);
}